// round 8
// baseline (speedup 1.0000x reference)
#include <cuda_runtime.h>
#include <cuda_fp16.h>
#include <math.h>

// Problem constants
#define BSZ 256
#define SEQ 64
#define HID 512
#define H2  1024
#define H4  2048
#define H8  4096
#define VOC 32000

// ---------------------------------------------------------------------------
// Scratch (no allocations allowed -> __device__ globals)
// ---------------------------------------------------------------------------
__device__ __half g_seq [SEQ * BSZ * HID];     // fp16 embedded sequence
__device__ float  g_gxf [SEQ * BSZ * H4];      // fp32 input proj (f cell)
__device__ float  g_gxb [SEQ * BSZ * H4];      // fp32 input proj (b cell)
__device__ __half g_comb[SEQ * BSZ * H2];      // fp16 concat(hf, hb)
__device__ __half g_hf[2][BSZ * HID];
__device__ float  g_cf[BSZ * HID];
__device__ __half g_hb[2][BSZ * HID];
__device__ float  g_cb[BSZ * HID];
__device__ __half g_hc[2][BSZ * H2];
__device__ float  g_cc[BSZ * H2];
// fp16 weight copies (converted once per launch)
__device__ __half g_wihf[H4 * HID];
__device__ __half g_whhf[H4 * HID];
__device__ __half g_wihb[H4 * HID];
__device__ __half g_whhb[H4 * HID];
__device__ __half g_wihc[H8 * H2];
__device__ __half g_whhc[H8 * H2];
__device__ __half g_wout[VOC * H2];

// ---------------------------------------------------------------------------
// fp32 -> fp16 conversion (4 elems/thread)
// ---------------------------------------------------------------------------
struct __align__(8) Half4 { __half2 a, b; };

__global__ __launch_bounds__(256)
void cvt_kernel(const float4* __restrict__ in, Half4* __restrict__ out, int n4)
{
    int i = blockIdx.x * blockDim.x + threadIdx.x;
    if (i >= n4) return;
    float4 v = in[i];
    Half4 h;
    h.a = __floats2half2_rn(v.x, v.y);
    h.b = __floats2half2_rn(v.z, v.w);
    out[i] = h;
}

// ---------------------------------------------------------------------------
// Embedding gather -> fp16, 4 elems/thread.
// ---------------------------------------------------------------------------
__global__ __launch_bounds__(256)
void embed_kernel(const int* __restrict__ x,
                  const float* __restrict__ W,
                  Half4* __restrict__ seq)
{
    const int H4v = HID / 4;
    int i = blockIdx.x * blockDim.x + threadIdx.x;
    if (i >= BSZ * SEQ * H4v) return;
    int row = i / H4v;
    int h4  = i - row * H4v;
    int idx = x[row];
    float4 v = make_float4(0.f, 0.f, 0.f, 0.f);
    if (idx != 0)
        v = reinterpret_cast<const float4*>(W)[(size_t)idx * H4v + h4];
    Half4 h;
    h.a = __floats2half2_rn(v.x, v.y);
    h.b = __floats2half2_rn(v.z, v.w);
    seq[i] = h;
}

// ---------------------------------------------------------------------------
// fp16 tensor-core GEMM with optional concat-K (two A / two W sources split
// at K0) and optional fused LSTM epilogue.
//   pre = [A0 | A1] @ [W0 | W1]^T  (+ gx)  (+ b0 + b1)
// BN fixed 128. BMT=64/8 warps (plain, projections/head) or BMT=32/4 warps
// (fused steps). mma.m16n8k16, ldmatrix for A and B fragments, 3-stage
// cp.async pipeline, smem [row][k] stride 40 halves (bank-conflict-free for
// all ldmatrix phases and cp.async stores).
// ---------------------------------------------------------------------------
struct StepSet {
    const __half* A0;    // k < K0
    const __half* A1;    // k >= K0 (may be null when K0 == K)
    const __half* W0;    // k < K0 ; null => block inactive
    const __half* W1;    // k >= K0
    const float*  D;     // fused: gx (B, 4*Hd) fp32 addend; may be null
    const float*  b0;    // per-column bias; may be null
    const float*  b1;
    float*        C;     // plain output (fp32)
    float*        cbuf;  // fused: cell state fp32
    __half*       hout;  // fused: next h fp16
    __half*       comb;  // fused: optional fp16 h scatter
    int combStride;
    int K;               // total K
    int K0;              // split point
    int Hd;              // fused hidden dim
    int jx;              // active gridDim.x
};

#define BKH 32    // k per tile, halves
#define KSTH 40   // smem k-stride in halves
#define STG 3

#define CP_ASYNC16(dst, src) \
    asm volatile("cp.async.ca.shared.global [%0], [%1], 16;\n" \
                 :: "r"(dst), "l"(src))
#define CP_COMMIT() asm volatile("cp.async.commit_group;\n" ::: "memory")
#define CP_WAIT(n)  asm volatile("cp.async.wait_group %0;\n" :: "n"(n) : "memory")

__device__ __forceinline__ void ldsm4(unsigned& r0, unsigned& r1,
                                      unsigned& r2, unsigned& r3,
                                      unsigned addr)
{
    asm volatile("ldmatrix.sync.aligned.m8n8.x4.shared.b16 {%0,%1,%2,%3}, [%4];"
                 : "=r"(r0), "=r"(r1), "=r"(r2), "=r"(r3) : "r"(addr));
}
__device__ __forceinline__ float sigf(float v) {
    return 1.0f / (1.0f + __expf(-v));
}

template<int BMT, int NW, bool FUSED>
__global__ __launch_bounds__(NW * 32)
void gemm_k(StepSet s0, StepSet s1, StepSet s2, int N)
{
    StepSet s = (blockIdx.z == 0) ? s0 : ((blockIdx.z == 1) ? s1 : s2);
    if (s.W0 == nullptr || (int)blockIdx.x >= s.jx) return;

    __shared__ __half As[STG][BMT][KSTH];
    __shared__ __half Bs[STG][128][KSTH];

    const int tid  = threadIdx.x;
    const int lane = tid & 31;
    const int wid  = tid >> 5;
    const int wm   = (NW == 8) ? (wid & 1) : 0;
    const int wn   = (NW == 8) ? (wid >> 1) : wid;
    const int m0   = blockIdx.y * BMT;
    const int n0   = blockIdx.x * 128;
    const int n0j  = blockIdx.x * 32;
    const int K    = s.K;
    const int K0   = s.K0;
    const int Hd   = s.Hd;
    const int T    = K / BKH;

    // A loader: BMT rows x 4 granules (8 halves each) == NW*32 chunks.
    const int a_row = tid >> 2;
    const int a_g   = tid & 3;
    const __half* a0row = s.A0 + (size_t)(m0 + a_row) * K0;
    const __half* a1row = s.A1 ? s.A1 + (size_t)(m0 + a_row) * (K - K0)
                               : (const __half*)nullptr;
    // B loader: 128 rows x 4 granules = 512 chunks; NB per thread.
    constexpr int NB = 512 / (NW * 32);
    int b_g[NB];
    const __half* b0row[NB];
    const __half* b1row[NB];
    unsigned b_dst[NB];
    int b_rowv[NB];
#pragma unroll
    for (int p = 0; p < NB; ++p) {
        int idx = tid + (NW * 32) * p;
        int row = idx >> 2;
        b_rowv[p] = row;
        b_g[p]    = idx & 3;
        int wrow;
        if (FUSED) {
            int wn_r = row >> 5;
            int t    = row & 31;
            int gate = t >> 3;
            int cc   = t & 7;
            int j    = n0j + wn_r * 8 + cc;
            wrow = gate * Hd + j;
        } else {
            wrow = n0 + row;
        }
        b0row[p] = s.W0 + (size_t)wrow * K0;
        b1row[p] = s.W1 ? s.W1 + (size_t)wrow * (K - K0)
                        : (const __half*)nullptr;
        b_dst[p] = (unsigned)__cvta_generic_to_shared(&Bs[0][row][b_g[p] * 8]);
    }

    unsigned a_dst = (unsigned)__cvta_generic_to_shared(&As[0][a_row][a_g * 8]);
    const unsigned a_stage = BMT * KSTH * 2;
    const unsigned b_stage = 128 * KSTH * 2;

    auto load_stage = [&](int st, int kt) {
        {
            int ka = kt * BKH + a_g * 8;
            const __half* src = (ka < K0) ? a0row + ka : a1row + (ka - K0);
            CP_ASYNC16(a_dst + st * a_stage, src);
        }
#pragma unroll
        for (int p = 0; p < NB; ++p) {
            int kb = kt * BKH + b_g[p] * 8;
            const __half* src = (kb < K0) ? b0row[p] + kb : b1row[p] + (kb - K0);
            CP_ASYNC16(b_dst[p] + st * b_stage, src);
        }
    };

    const unsigned as_base = (unsigned)__cvta_generic_to_shared(&As[0][0][0]);
    const unsigned bs_base = (unsigned)__cvta_generic_to_shared(&Bs[0][0][0]);

    float acc[2][4][4];
#pragma unroll
    for (int i = 0; i < 2; ++i)
#pragma unroll
        for (int j = 0; j < 4; ++j)
#pragma unroll
            for (int r = 0; r < 4; ++r) acc[i][j][r] = 0.f;

    // prologue
#pragma unroll
    for (int st = 0; st < STG - 1; ++st) {
        if (st < T) load_stage(st, st);
        CP_COMMIT();
    }

    // ldmatrix lane addressing
    const int lm_rowA = lane & 15;
    const int lm_kA   = (lane >> 4) << 3;
    const int lm_rowB = (lane & 7) + ((lane >> 4) & 1) * 8;
    const int lm_kB   = ((lane >> 3) & 1) * 8;

    for (int kt = 0; kt < T; ++kt) {
        CP_WAIT(STG - 2);
        __syncthreads();
        const int buf = kt % STG;
#pragma unroll
        for (int ks = 0; ks < 2; ++ks) {
            const int c = ks * 16;
            unsigned a[2][4];
#pragma unroll
            for (int mt = 0; mt < 2; ++mt) {
                int r0 = wm * 32 + mt * 16;
                unsigned addr = as_base + (unsigned)buf * a_stage +
                    ((r0 + lm_rowA) * KSTH + c + lm_kA) * 2;
                ldsm4(a[mt][0], a[mt][1], a[mt][2], a[mt][3], addr);
            }
            unsigned bb[2][4];
#pragma unroll
            for (int pr = 0; pr < 2; ++pr) {
                int nb = wn * 32 + pr * 16;
                unsigned addr = bs_base + (unsigned)buf * b_stage +
                    ((nb + lm_rowB) * KSTH + c + lm_kB) * 2;
                ldsm4(bb[pr][0], bb[pr][1], bb[pr][2], bb[pr][3], addr);
            }
#pragma unroll
            for (int nt = 0; nt < 4; ++nt) {
                unsigned bf0 = bb[nt >> 1][(nt & 1) * 2 + 0];
                unsigned bf1 = bb[nt >> 1][(nt & 1) * 2 + 1];
#pragma unroll
                for (int mt = 0; mt < 2; ++mt) {
                    asm volatile(
                        "mma.sync.aligned.m16n8k16.row.col.f32.f16.f16.f32 "
                        "{%0,%1,%2,%3}, {%4,%5,%6,%7}, {%8,%9}, {%0,%1,%2,%3};"
                        : "+f"(acc[mt][nt][0]), "+f"(acc[mt][nt][1]),
                          "+f"(acc[mt][nt][2]), "+f"(acc[mt][nt][3])
                        : "r"(a[mt][0]), "r"(a[mt][1]),
                          "r"(a[mt][2]), "r"(a[mt][3]),
                          "r"(bf0), "r"(bf1));
                }
            }
        }
        const int nk = kt + STG - 1;
        if (nk < T) load_stage(nk % STG, nk);
        CP_COMMIT();
    }

    if (!FUSED) {
        // Plain epilogue -> fp32 C
#pragma unroll
        for (int mt = 0; mt < 2; ++mt) {
#pragma unroll
            for (int nt = 0; nt < 4; ++nt) {
                int m = m0 + wm * 32 + mt * 16 + (lane >> 2);
                int n = n0 + wn * 32 + nt * 8 + (lane & 3) * 2;
#pragma unroll
                for (int rr = 0; rr < 2; ++rr) {
                    int mm = m + rr * 8;
                    size_t off = (size_t)mm * N + n;
                    float v0 = acc[mt][nt][rr * 2 + 0];
                    float v1 = acc[mt][nt][rr * 2 + 1];
                    if (s.b0) { v0 += s.b0[n]; v1 += s.b0[n + 1]; }
                    if (s.b1) { v0 += s.b1[n]; v1 += s.b1[n + 1]; }
                    *reinterpret_cast<float2*>(s.C + off) = make_float2(v0, v1);
                }
            }
        }
    } else {
        // Fused LSTM epilogue: nt == gate (i,f,g,o); j pair per thread.
        const int j = n0j + wn * 8 + (lane & 3) * 2;
        float2 badd[4];
#pragma unroll
        for (int g = 0; g < 4; ++g) {
            badd[g] = make_float2(0.f, 0.f);
            if (s.b0) {
                float2 x0 = *reinterpret_cast<const float2*>(s.b0 + g * Hd + j);
                float2 x1 = *reinterpret_cast<const float2*>(s.b1 + g * Hd + j);
                badd[g] = make_float2(x0.x + x1.x, x0.y + x1.y);
            }
        }
#pragma unroll
        for (int mt = 0; mt < 2; ++mt) {
#pragma unroll
            for (int rr = 0; rr < 2; ++rr) {
                int m = m0 + wm * 32 + mt * 16 + (lane >> 2) + rr * 8;
                float2 di = badd[0], df = badd[1], dg = badd[2], do_ = badd[3];
                if (s.D) {
                    const float* gx = s.D + (size_t)m * 4 * Hd;
                    float2 t;
                    t = *reinterpret_cast<const float2*>(gx +          j);
                    di.x += t.x; di.y += t.y;
                    t = *reinterpret_cast<const float2*>(gx +     Hd + j);
                    df.x += t.x; df.y += t.y;
                    t = *reinterpret_cast<const float2*>(gx + 2 * Hd + j);
                    dg.x += t.x; dg.y += t.y;
                    t = *reinterpret_cast<const float2*>(gx + 3 * Hd + j);
                    do_.x += t.x; do_.y += t.y;
                }
                float2 cv = *reinterpret_cast<const float2*>(
                    s.cbuf + (size_t)m * Hd + j);

                float pi0 = acc[mt][0][rr * 2 + 0] + di.x;
                float pi1 = acc[mt][0][rr * 2 + 1] + di.y;
                float pf0 = acc[mt][1][rr * 2 + 0] + df.x;
                float pf1 = acc[mt][1][rr * 2 + 1] + df.y;
                float pg0 = acc[mt][2][rr * 2 + 0] + dg.x;
                float pg1 = acc[mt][2][rr * 2 + 1] + dg.y;
                float po0 = acc[mt][3][rr * 2 + 0] + do_.x;
                float po1 = acc[mt][3][rr * 2 + 1] + do_.y;

                float cn0 = sigf(pf0) * cv.x + sigf(pi0) * tanhf(pg0);
                float cn1 = sigf(pf1) * cv.y + sigf(pi1) * tanhf(pg1);
                float hn0 = sigf(po0) * tanhf(cn0);
                float hn1 = sigf(po1) * tanhf(cn1);

                *reinterpret_cast<float2*>(s.cbuf + (size_t)m * Hd + j) =
                    make_float2(cn0, cn1);
                __half2 hh = __floats2half2_rn(hn0, hn1);
                *reinterpret_cast<__half2*>(s.hout + (size_t)m * Hd + j) = hh;
                if (s.comb)
                    *reinterpret_cast<__half2*>(
                        s.comb + (size_t)m * s.combStride + j) = hh;
            }
        }
    }
}

// ---------------------------------------------------------------------------
// kernel_launch
// ---------------------------------------------------------------------------
extern "C" void kernel_launch(void* const* d_in, const int* in_sizes, int n_in,
                              void* d_out, int out_size)
{
    const int*   x     = (const int*)  d_in[0];
    const float* W_emb = (const float*)d_in[1];
    const float* Wih_f = (const float*)d_in[2];
    const float* Whh_f = (const float*)d_in[3];
    const float* bih_f = (const float*)d_in[4];
    const float* bhh_f = (const float*)d_in[5];
    const float* Wih_b = (const float*)d_in[6];
    const float* Whh_b = (const float*)d_in[7];
    const float* bih_b = (const float*)d_in[8];
    const float* bhh_b = (const float*)d_in[9];
    const float* Wih_c = (const float*)d_in[10];
    const float* Whh_c = (const float*)d_in[11];
    const float* bih_c = (const float*)d_in[12];
    const float* bhh_c = (const float*)d_in[13];
    const float* Wout  = (const float*)d_in[14];
    const float* bout  = (const float*)d_in[15];
    const float* h0f   = (const float*)d_in[16];
    const float* c0f   = (const float*)d_in[17];
    const float* h0b   = (const float*)d_in[18];
    const float* c0b   = (const float*)d_in[19];
    const float* h0c   = (const float*)d_in[20];
    const float* c0c   = (const float*)d_in[21];
    float* out = (float*)d_out;

    __half *seq, *comb, *hf, *hb, *hc;
    __half *wihf, *whhf, *wihb, *whhb, *wihc, *whhc, *wout;
    float *gxf, *gxb, *cf, *cb, *cc;
    cudaGetSymbolAddress((void**)&seq,  g_seq);
    cudaGetSymbolAddress((void**)&gxf,  g_gxf);
    cudaGetSymbolAddress((void**)&gxb,  g_gxb);
    cudaGetSymbolAddress((void**)&comb, g_comb);
    cudaGetSymbolAddress((void**)&hf,   g_hf);
    cudaGetSymbolAddress((void**)&cf,   g_cf);
    cudaGetSymbolAddress((void**)&hb,   g_hb);
    cudaGetSymbolAddress((void**)&cb,   g_cb);
    cudaGetSymbolAddress((void**)&hc,   g_hc);
    cudaGetSymbolAddress((void**)&cc,   g_cc);
    cudaGetSymbolAddress((void**)&wihf, g_wihf);
    cudaGetSymbolAddress((void**)&whhf, g_whhf);
    cudaGetSymbolAddress((void**)&wihb, g_wihb);
    cudaGetSymbolAddress((void**)&whhb, g_whhb);
    cudaGetSymbolAddress((void**)&wihc, g_wihc);
    cudaGetSymbolAddress((void**)&whhc, g_whhc);
    cudaGetSymbolAddress((void**)&wout, g_wout);

    __half* hfb[2] = {hf, hf + BSZ * HID};
    __half* hbb[2] = {hb, hb + BSZ * HID};
    __half* hcb[2] = {hc, hc + BSZ * H2};

    auto cvt = [](const float* in, __half* out_, int n) {
        int n4 = n / 4;
        cvt_kernel<<<(n4 + 255) / 256, 256>>>(
            (const float4*)in, (Half4*)out_, n4);
    };

    cvt(Wih_f, wihf, H4 * HID);
    cvt(Whh_f, whhf, H4 * HID);
    cvt(Wih_b, wihb, H4 * HID);
    cvt(Whh_b, whhb, H4 * HID);
    cvt(Wih_c, wihc, H8 * H2);
    cvt(Whh_c, whhc, H8 * H2);
    cvt(Wout,  wout, VOC * H2);
    cvt(h0f, hfb[0], BSZ * HID);
    cvt(h0b, hbb[0], BSZ * HID);
    cvt(h0c, hcb[0], BSZ * H2);

    cudaMemcpyAsync(cf, c0f, BSZ * HID * sizeof(float), cudaMemcpyDeviceToDevice, 0);
    cudaMemcpyAsync(cb, c0b, BSZ * HID * sizeof(float), cudaMemcpyDeviceToDevice, 0);
    cudaMemcpyAsync(cc, c0c, BSZ * H2  * sizeof(float), cudaMemcpyDeviceToDevice, 0);

    {
        int total4 = BSZ * SEQ * (HID / 4);
        embed_kernel<<<(total4 + 255) / 256, 256>>>(x, W_emb, (Half4*)seq);
    }

    StepSet Z = {};

    // Batched input projections for f and b cells (plain, BM=64)
    {
        StepSet sf = Z;
        sf.A0 = seq; sf.W0 = wihf; sf.b0 = bih_f; sf.b1 = bhh_f; sf.C = gxf;
        sf.K = HID; sf.K0 = HID; sf.jx = H4 / 128;
        StepSet sb = sf;
        sb.W0 = wihb; sb.b0 = bih_b; sb.b1 = bhh_b; sb.C = gxb;
        dim3 grid(H4 / 128, (SEQ * BSZ) / 64, 2);
        gemm_k<64, 8, false><<<grid, 256>>>(sf, sb, sb, H4);
    }

    // Pipelined recurrence: launch u does {f step u, b step u, comb step u-1}
    for (int u = 0; u <= SEQ; ++u) {
        StepSet f = Z, b = Z, c = Z;
        if (u < SEQ) {
            f.A0 = hfb[u & 1]; f.W0 = whhf;
            f.D = gxf + (size_t)u * BSZ * H4;
            f.cbuf = cf; f.hout = hfb[(u + 1) & 1];
            f.comb = comb + (size_t)u * BSZ * H2; f.combStride = H2;
            f.K = HID; f.K0 = HID; f.Hd = HID; f.jx = HID / 32;

            b = f;
            b.A0 = hbb[u & 1]; b.W0 = whhb;
            b.D = gxb + (size_t)(SEQ - 1 - u) * BSZ * H4;
            b.cbuf = cb; b.hout = hbb[(u + 1) & 1];
            b.comb = comb + (size_t)u * BSZ * H2 + HID;
        }
        if (u > 0) {
            int t = u - 1;
            c.A0 = hcb[t & 1]; c.A1 = comb + (size_t)t * BSZ * H2;
            c.W0 = whhc; c.W1 = wihc;
            c.b0 = bih_c; c.b1 = bhh_c;
            c.cbuf = cc; c.hout = hcb[u & 1];
            c.K = 2 * H2; c.K0 = H2; c.Hd = H2; c.jx = H2 / 32;
        }
        dim3 grid(H2 / 32, BSZ / 32, 3);
        gemm_k<32, 4, true><<<grid, 128>>>(f, b, c, 0);
    }

    // output head: out = hc_final @ Wout^T + bout (final hc in buffer 0)
    {
        StepSet so = Z;
        so.A0 = hcb[0]; so.W0 = wout; so.b0 = bout; so.C = out;
        so.K = H2; so.K0 = H2; so.jx = VOC / 128;
        dim3 grid(VOC / 128, BSZ / 64, 1);
        gemm_k<64, 8, false><<<grid, 256>>>(so, so, so, VOC);
    }
}

// round 9
// speedup vs baseline: 1.0652x; 1.0652x over previous
#include <cuda_runtime.h>
#include <cuda_fp16.h>
#include <math.h>

// Problem constants
#define BSZ 256
#define SEQ 64
#define HID 512
#define H2  1024
#define H4  2048
#define H8  4096
#define VOC 32000

// ---------------------------------------------------------------------------
// Scratch (no allocations allowed -> __device__ globals)
// ---------------------------------------------------------------------------
__device__ __half g_seq [SEQ * BSZ * HID];     // fp16 embedded sequence
__device__ float  g_gxf [SEQ * BSZ * H4];      // fp32 input proj (f cell)
__device__ float  g_gxb [SEQ * BSZ * H4];      // fp32 input proj (b cell)
__device__ float  g_gxc [SEQ * BSZ * H8];      // fp32 input proj (combiner)
__device__ __half g_comb[SEQ * BSZ * H2];      // fp16 concat(hf, hb)
__device__ __half g_hf[2][BSZ * HID];
__device__ float  g_cf[BSZ * HID];
__device__ __half g_hb[2][BSZ * HID];
__device__ float  g_cb[BSZ * HID];
__device__ __half g_hc[2][BSZ * H2];
__device__ float  g_cc[BSZ * H2];
// fp16 weight copies (converted once per launch)
__device__ __half g_wihf[H4 * HID];
__device__ __half g_whhf[H4 * HID];
__device__ __half g_wihb[H4 * HID];
__device__ __half g_whhb[H4 * HID];
__device__ __half g_wihc[H8 * H2];
__device__ __half g_whhc[H8 * H2];
__device__ __half g_wout[VOC * H2];

// ---------------------------------------------------------------------------
// fp32 -> fp16 conversion (4 elems/thread)
// ---------------------------------------------------------------------------
struct __align__(8) Half4 { __half2 a, b; };

__global__ __launch_bounds__(256)
void cvt_kernel(const float4* __restrict__ in, Half4* __restrict__ out, int n4)
{
    int i = blockIdx.x * blockDim.x + threadIdx.x;
    if (i >= n4) return;
    float4 v = in[i];
    Half4 h;
    h.a = __floats2half2_rn(v.x, v.y);
    h.b = __floats2half2_rn(v.z, v.w);
    out[i] = h;
}

// ---------------------------------------------------------------------------
// Embedding gather -> fp16, 4 elems/thread.
// ---------------------------------------------------------------------------
__global__ __launch_bounds__(256)
void embed_kernel(const int* __restrict__ x,
                  const float* __restrict__ W,
                  Half4* __restrict__ seq)
{
    const int H4v = HID / 4;
    int i = blockIdx.x * blockDim.x + threadIdx.x;
    if (i >= BSZ * SEQ * H4v) return;
    int row = i / H4v;
    int h4  = i - row * H4v;
    int idx = x[row];
    float4 v = make_float4(0.f, 0.f, 0.f, 0.f);
    if (idx != 0)
        v = reinterpret_cast<const float4*>(W)[(size_t)idx * H4v + h4];
    Half4 h;
    h.a = __floats2half2_rn(v.x, v.y);
    h.b = __floats2half2_rn(v.z, v.w);
    seq[i] = h;
}

// ---------------------------------------------------------------------------
// fp16 tensor-core GEMM, 64x128 block tile, BK=32 halves, 256 threads
// (8 warps, warp tile 32x32), mma.m16n8k16, ldmatrix for A AND B fragments,
// 3-stage cp.async pipeline. Smem [row][k] stride 40 halves.
//
// Plain (FUSED=false): C(f32) = A @ W^T [+b0] [+b1]
// Fused (FUSED=true):  gate-interleaved columns; LSTM epilogue with fp32 gx
//   addend + fp32 cell state; writes h (fp16) and optional comb scatter.
// Three parameter sets selected by blockIdx.z; set inactive => early exit.
// ---------------------------------------------------------------------------
struct GemmSet {
    const __half* A;
    const __half* W;     // null => block inactive
    const float*  D;     // fused: gx (B, 4*Hd) fp32
    const float*  b0;    // plain only
    const float*  b1;    // plain only
    float*        C;     // plain only (fp32 out)
    float*        cbuf;  // fused: cell state fp32, read+write
    __half*       hout;  // fused: next h fp16
    __half*       comb;  // fused: optional fp16 h scatter
    int           combStride;
    int           Hd;    // fused hidden dim
    int           jx;    // active gridDim.x
};

#define BM 64
#define BKH 32    // k per tile, in halves
#define KSTH 40   // smem k-stride in halves (32 + 8 pad)
#define STG 3

#define CP_ASYNC16(dst, src) \
    asm volatile("cp.async.ca.shared.global [%0], [%1], 16;\n" \
                 :: "r"(dst), "l"(src))
#define CP_COMMIT() asm volatile("cp.async.commit_group;\n" ::: "memory")
#define CP_WAIT(n)  asm volatile("cp.async.wait_group %0;\n" :: "n"(n) : "memory")

__device__ __forceinline__ void ldsm4(unsigned& r0, unsigned& r1,
                                      unsigned& r2, unsigned& r3,
                                      unsigned addr)
{
    asm volatile("ldmatrix.sync.aligned.m8n8.x4.shared.b16 {%0,%1,%2,%3}, [%4];"
                 : "=r"(r0), "=r"(r1), "=r"(r2), "=r"(r3) : "r"(addr));
}
__device__ __forceinline__ float sigf(float v) {
    return 1.0f / (1.0f + __expf(-v));
}

template<bool FUSED>
__global__ __launch_bounds__(256)
void gemm_f16(GemmSet s0, GemmSet s1, GemmSet s2, int N, int K)
{
    GemmSet s = (blockIdx.z == 0) ? s0 : ((blockIdx.z == 1) ? s1 : s2);
    if (s.W == nullptr || (int)blockIdx.x >= s.jx) return;
    if (FUSED) K = s.Hd;    // fused: K equals the cell's hidden size

    __shared__ __half As[STG][BM][KSTH];
    __shared__ __half Bs[STG][128][KSTH];

    const int tid  = threadIdx.x;
    const int lane = tid & 31;
    const int wid  = tid >> 5;
    const int wm   = wid & 1;        // m offset wm*32
    const int wn   = wid >> 1;       // n offset wn*32
    const int m0   = blockIdx.y * BM;
    const int n0   = blockIdx.x * 128;   // plain column base
    const int n0j  = blockIdx.x * 32;    // fused j base
    const int Hd   = s.Hd;
    const int T    = K / BKH;

    // A loader: 64 rows x 4 granules (8 halves = 16B each)
    const int a_row = tid >> 2;
    const int a_g   = tid & 3;
    const __half* a_src = s.A + (size_t)(m0 + a_row) * K + a_g * 8;
    // B loader: 128 rows x 4 granules, 2 per thread
    int b_row[2], b_g[2];
    const __half* b_src[2];
#pragma unroll
    for (int p = 0; p < 2; ++p) {
        int idx = tid + 256 * p;
        int row = idx >> 2;
        b_row[p] = row;
        b_g[p]   = idx & 3;
        int wrow;
        if (FUSED) {
            int wn_r = row >> 5;
            int t    = row & 31;
            int gate = t >> 3;
            int cc   = t & 7;
            int j    = n0j + wn_r * 8 + cc;
            wrow = gate * Hd + j;
        } else {
            wrow = n0 + row;
        }
        b_src[p] = s.W + (size_t)wrow * K + b_g[p] * 8;
    }

    unsigned a_dst = (unsigned)__cvta_generic_to_shared(&As[0][a_row][a_g * 8]);
    unsigned b_dst[2];
    b_dst[0] = (unsigned)__cvta_generic_to_shared(&Bs[0][b_row[0]][b_g[0] * 8]);
    b_dst[1] = (unsigned)__cvta_generic_to_shared(&Bs[0][b_row[1]][b_g[1] * 8]);
    const unsigned a_stage = BM * KSTH * 2;
    const unsigned b_stage = 128 * KSTH * 2;

    auto load_stage = [&](int st, int kt) {
        CP_ASYNC16(a_dst + st * a_stage, a_src + kt * BKH);
        CP_ASYNC16(b_dst[0] + st * b_stage, b_src[0] + kt * BKH);
        CP_ASYNC16(b_dst[1] + st * b_stage, b_src[1] + kt * BKH);
    };

    const unsigned as_base = (unsigned)__cvta_generic_to_shared(&As[0][0][0]);
    const unsigned bs_base = (unsigned)__cvta_generic_to_shared(&Bs[0][0][0]);

    float acc[2][4][4];
#pragma unroll
    for (int i = 0; i < 2; ++i)
#pragma unroll
        for (int j = 0; j < 4; ++j)
#pragma unroll
            for (int r = 0; r < 4; ++r) acc[i][j][r] = 0.f;

    // prologue
#pragma unroll
    for (int st = 0; st < STG - 1; ++st) {
        if (st < T) load_stage(st, st);
        CP_COMMIT();
    }

    // ldmatrix lane addressing (constant per thread)
    const int lm_rowA = lane & 15;
    const int lm_kA   = (lane >> 4) << 3;
    const int lm_rowB = (lane & 7) + ((lane >> 4) & 1) * 8;
    const int lm_kB   = ((lane >> 3) & 1) * 8;

    for (int kt = 0; kt < T; ++kt) {
        CP_WAIT(STG - 2);
        __syncthreads();
        const int buf = kt % STG;
#pragma unroll
        for (int ks = 0; ks < 2; ++ks) {
            const int c = ks * 16;
            unsigned a[2][4];
#pragma unroll
            for (int mt = 0; mt < 2; ++mt) {
                int r0 = wm * 32 + mt * 16;
                unsigned addr = as_base + (unsigned)buf * a_stage +
                    ((r0 + lm_rowA) * KSTH + c + lm_kA) * 2;
                ldsm4(a[mt][0], a[mt][1], a[mt][2], a[mt][3], addr);
            }
            unsigned bb[2][4];
#pragma unroll
            for (int pr = 0; pr < 2; ++pr) {
                int nb = wn * 32 + pr * 16;
                unsigned addr = bs_base + (unsigned)buf * b_stage +
                    ((nb + lm_rowB) * KSTH + c + lm_kB) * 2;
                ldsm4(bb[pr][0], bb[pr][1], bb[pr][2], bb[pr][3], addr);
            }
#pragma unroll
            for (int nt = 0; nt < 4; ++nt) {
                unsigned bf0 = bb[nt >> 1][(nt & 1) * 2 + 0];
                unsigned bf1 = bb[nt >> 1][(nt & 1) * 2 + 1];
#pragma unroll
                for (int mt = 0; mt < 2; ++mt) {
                    asm volatile(
                        "mma.sync.aligned.m16n8k16.row.col.f32.f16.f16.f32 "
                        "{%0,%1,%2,%3}, {%4,%5,%6,%7}, {%8,%9}, {%0,%1,%2,%3};"
                        : "+f"(acc[mt][nt][0]), "+f"(acc[mt][nt][1]),
                          "+f"(acc[mt][nt][2]), "+f"(acc[mt][nt][3])
                        : "r"(a[mt][0]), "r"(a[mt][1]),
                          "r"(a[mt][2]), "r"(a[mt][3]),
                          "r"(bf0), "r"(bf1));
                }
            }
        }
        const int nk = kt + STG - 1;
        if (nk < T) load_stage(nk % STG, nk);
        CP_COMMIT();
    }

    if (!FUSED) {
        // Plain epilogue -> fp32 C
#pragma unroll
        for (int mt = 0; mt < 2; ++mt) {
#pragma unroll
            for (int nt = 0; nt < 4; ++nt) {
                int m = m0 + wm * 32 + mt * 16 + (lane >> 2);
                int n = n0 + wn * 32 + nt * 8 + (lane & 3) * 2;
#pragma unroll
                for (int rr = 0; rr < 2; ++rr) {
                    int mm = m + rr * 8;
                    size_t off = (size_t)mm * N + n;
                    float v0 = acc[mt][nt][rr * 2 + 0];
                    float v1 = acc[mt][nt][rr * 2 + 1];
                    if (s.b0) { v0 += s.b0[n]; v1 += s.b0[n + 1]; }
                    if (s.b1) { v0 += s.b1[n]; v1 += s.b1[n + 1]; }
                    *reinterpret_cast<float2*>(s.C + off) = make_float2(v0, v1);
                }
            }
        }
    } else {
        // Fused LSTM epilogue: nt == gate (i,f,g,o); j pair per thread.
        const int j = n0j + wn * 8 + (lane & 3) * 2;
#pragma unroll
        for (int mt = 0; mt < 2; ++mt) {
#pragma unroll
            for (int rr = 0; rr < 2; ++rr) {
                int m = m0 + wm * 32 + mt * 16 + (lane >> 2) + rr * 8;
                const float* gx = s.D + (size_t)m * 4 * Hd;
                float2 di = *reinterpret_cast<const float2*>(gx +          j);
                float2 df = *reinterpret_cast<const float2*>(gx +     Hd + j);
                float2 dg = *reinterpret_cast<const float2*>(gx + 2 * Hd + j);
                float2 do_= *reinterpret_cast<const float2*>(gx + 3 * Hd + j);
                float2 cv = *reinterpret_cast<const float2*>(
                    s.cbuf + (size_t)m * Hd + j);

                float pi0 = acc[mt][0][rr * 2 + 0] + di.x;
                float pi1 = acc[mt][0][rr * 2 + 1] + di.y;
                float pf0 = acc[mt][1][rr * 2 + 0] + df.x;
                float pf1 = acc[mt][1][rr * 2 + 1] + df.y;
                float pg0 = acc[mt][2][rr * 2 + 0] + dg.x;
                float pg1 = acc[mt][2][rr * 2 + 1] + dg.y;
                float po0 = acc[mt][3][rr * 2 + 0] + do_.x;
                float po1 = acc[mt][3][rr * 2 + 1] + do_.y;

                float cn0 = sigf(pf0) * cv.x + sigf(pi0) * tanhf(pg0);
                float cn1 = sigf(pf1) * cv.y + sigf(pi1) * tanhf(pg1);
                float hn0 = sigf(po0) * tanhf(cn0);
                float hn1 = sigf(po1) * tanhf(cn1);

                *reinterpret_cast<float2*>(s.cbuf + (size_t)m * Hd + j) =
                    make_float2(cn0, cn1);
                __half2 hh = __floats2half2_rn(hn0, hn1);
                *reinterpret_cast<__half2*>(s.hout + (size_t)m * Hd + j) = hh;
                if (s.comb)
                    *reinterpret_cast<__half2*>(
                        s.comb + (size_t)m * s.combStride + j) = hh;
            }
        }
    }
}

// ---------------------------------------------------------------------------
// kernel_launch
// ---------------------------------------------------------------------------
extern "C" void kernel_launch(void* const* d_in, const int* in_sizes, int n_in,
                              void* d_out, int out_size)
{
    const int*   x     = (const int*)  d_in[0];
    const float* W_emb = (const float*)d_in[1];
    const float* Wih_f = (const float*)d_in[2];
    const float* Whh_f = (const float*)d_in[3];
    const float* bih_f = (const float*)d_in[4];
    const float* bhh_f = (const float*)d_in[5];
    const float* Wih_b = (const float*)d_in[6];
    const float* Whh_b = (const float*)d_in[7];
    const float* bih_b = (const float*)d_in[8];
    const float* bhh_b = (const float*)d_in[9];
    const float* Wih_c = (const float*)d_in[10];
    const float* Whh_c = (const float*)d_in[11];
    const float* bih_c = (const float*)d_in[12];
    const float* bhh_c = (const float*)d_in[13];
    const float* Wout  = (const float*)d_in[14];
    const float* bout  = (const float*)d_in[15];
    const float* h0f   = (const float*)d_in[16];
    const float* c0f   = (const float*)d_in[17];
    const float* h0b   = (const float*)d_in[18];
    const float* c0b   = (const float*)d_in[19];
    const float* h0c   = (const float*)d_in[20];
    const float* c0c   = (const float*)d_in[21];
    float* out = (float*)d_out;

    __half *seq, *comb, *hf, *hb, *hc;
    __half *wihf, *whhf, *wihb, *whhb, *wihc, *whhc, *wout;
    float *gxf, *gxb, *gxc, *cf, *cb, *cc;
    cudaGetSymbolAddress((void**)&seq,  g_seq);
    cudaGetSymbolAddress((void**)&gxf,  g_gxf);
    cudaGetSymbolAddress((void**)&gxb,  g_gxb);
    cudaGetSymbolAddress((void**)&gxc,  g_gxc);
    cudaGetSymbolAddress((void**)&comb, g_comb);
    cudaGetSymbolAddress((void**)&hf,   g_hf);
    cudaGetSymbolAddress((void**)&cf,   g_cf);
    cudaGetSymbolAddress((void**)&hb,   g_hb);
    cudaGetSymbolAddress((void**)&cb,   g_cb);
    cudaGetSymbolAddress((void**)&hc,   g_hc);
    cudaGetSymbolAddress((void**)&cc,   g_cc);
    cudaGetSymbolAddress((void**)&wihf, g_wihf);
    cudaGetSymbolAddress((void**)&whhf, g_whhf);
    cudaGetSymbolAddress((void**)&wihb, g_wihb);
    cudaGetSymbolAddress((void**)&whhb, g_whhb);
    cudaGetSymbolAddress((void**)&wihc, g_wihc);
    cudaGetSymbolAddress((void**)&whhc, g_whhc);
    cudaGetSymbolAddress((void**)&wout, g_wout);

    __half* hfb[2] = {hf, hf + BSZ * HID};
    __half* hbb[2] = {hb, hb + BSZ * HID};
    __half* hcb[2] = {hc, hc + BSZ * H2};

    auto cvt = [](const float* in, __half* out_, int n) {
        int n4 = n / 4;
        cvt_kernel<<<(n4 + 255) / 256, 256>>>(
            (const float4*)in, (Half4*)out_, n4);
    };

    cvt(Wih_f, wihf, H4 * HID);
    cvt(Whh_f, whhf, H4 * HID);
    cvt(Wih_b, wihb, H4 * HID);
    cvt(Whh_b, whhb, H4 * HID);
    cvt(Wih_c, wihc, H8 * H2);
    cvt(Whh_c, whhc, H8 * H2);
    cvt(Wout,  wout, VOC * H2);
    cvt(h0f, hfb[0], BSZ * HID);
    cvt(h0b, hbb[0], BSZ * HID);
    cvt(h0c, hcb[0], BSZ * H2);

    cudaMemcpyAsync(cf, c0f, BSZ * HID * sizeof(float), cudaMemcpyDeviceToDevice, 0);
    cudaMemcpyAsync(cb, c0b, BSZ * HID * sizeof(float), cudaMemcpyDeviceToDevice, 0);
    cudaMemcpyAsync(cc, c0c, BSZ * H2  * sizeof(float), cudaMemcpyDeviceToDevice, 0);

    {
        int total4 = BSZ * SEQ * (HID / 4);
        embed_kernel<<<(total4 + 255) / 256, 256>>>(x, W_emb, (Half4*)seq);
    }

    GemmSet Z = {};

    // Batched input projections for f and b cells (plain)
    {
        GemmSet sf = Z;
        sf.A = seq; sf.W = wihf; sf.b0 = bih_f; sf.b1 = bhh_f; sf.C = gxf;
        sf.jx = H4 / 128;
        GemmSet sb = sf;
        sb.W = wihb; sb.b0 = bih_b; sb.b1 = bhh_b; sb.C = gxb;
        dim3 grid(H4 / 128, (SEQ * BSZ) / BM, 2);
        gemm_f16<false><<<grid, 256>>>(sf, sb, Z, H4, HID);
    }

    // Batched input projection for combiner cell (plain)
    {
        GemmSet sc = Z;
        sc.A = comb; sc.W = wihc; sc.b0 = bih_c; sc.b1 = bhh_c; sc.C = gxc;
        sc.jx = H8 / 128;
        // NOTE: must run BEFORE comb is consumed, but comb is produced by the
        // step loop; so this projection is done per-wave inside the loop?  No:
        // it only depends on comb, which is written by f/b steps.  We instead
        // run it AFTER the f/b steps complete (see below).
        (void)sc;
    }

    // Phase 1: f/b recurrences only (z=2), producing comb
    // Phase 2 needs gxc = comb @ Wih_c^T, so we interleave:
    //   - run all f/b steps (64 launches of z=2)  ... but that forfeits the
    //     merge.  Instead: merged pipeline with gxc computed per-step slab.
    //
    // Merged pipeline: launch u does { f step u, b step u, comb step u-1 }.
    // comb step t consumes gxc slab t, which requires comb slab t (written in
    // launch t) projected through Wih_c.  We fold that projection into the
    // same launch as a 4th z-slice operating on slab t = u-1 (plain GEMM on
    // 256 rows).  z layout: 0=f, 1=b, 2=cproj(slab u-1) -- and the comb LSTM
    // step for slab u-1 runs in launch u+1 (z handled via second kernel).
    //
    // Simpler correct schedule (launch k dependencies within stream order):
    //   launch u (z=3):  f[u], b[u], cstep[u-2]
    //   launch u (z=1):  cproj[u-1]   (after f/b of u-1 completed in launch u-1)
    // Both in the same stream, so ordering is: ... f/b[u-1] -> cproj[u-1] ->
    // (next launch) cstep[u-1] ...
    for (int u = 0; u <= SEQ + 1; ++u) {
        // merged step launch: f[u], b[u], cstep[u-2]
        GemmSet f = Z, b = Z, c = Z;
        if (u < SEQ) {
            f.A = hfb[u & 1]; f.W = whhf;
            f.D = gxf + (size_t)u * BSZ * H4;
            f.cbuf = cf; f.hout = hfb[(u + 1) & 1];
            f.comb = comb + (size_t)u * BSZ * H2; f.combStride = H2;
            f.Hd = HID; f.jx = HID / 32;

            b = f;
            b.A = hbb[u & 1]; b.W = whhb;
            b.D = gxb + (size_t)(SEQ - 1 - u) * BSZ * H4;
            b.cbuf = cb; b.hout = hbb[(u + 1) & 1];
            b.comb = comb + (size_t)u * BSZ * H2 + HID;
        }
        if (u >= 2) {
            int t = u - 2;
            c.A = hcb[t & 1]; c.W = whhc;
            c.D = gxc + (size_t)t * BSZ * H8;
            c.cbuf = cc; c.hout = hcb[(t + 1) & 1];
            c.Hd = H2; c.jx = H2 / 32;
        }
        if (u < SEQ || u >= 2) {
            dim3 grid(H2 / 32, BSZ / BM, 3);
            gemm_f16<true><<<grid, 256>>>(f, b, c, 0, 0);
        }
        // combiner input projection for slab u-1 (comb slab written above
        // in launch u-1; stream order guarantees visibility)
        if (u >= 1 && u <= SEQ) {
            int t = u - 1;
            GemmSet sc = Z;
            sc.A = comb + (size_t)t * BSZ * H2;
            sc.W = wihc; sc.b0 = bih_c; sc.b1 = bhh_c;
            sc.C = gxc + (size_t)t * BSZ * H8;
            sc.jx = H8 / 128;
            dim3 grid(H8 / 128, BSZ / BM, 1);
            gemm_f16<false><<<grid, 256>>>(sc, Z, Z, H8, H2);
        }
    }

    // output head: out = hc_final @ Wout^T + bout
    // final combiner step was t = SEQ-1, writing hcb[SEQ & 1] = hcb[0]
    {
        GemmSet so = Z;
        so.A = hcb[0]; so.W = wout; so.b0 = bout; so.C = out;
        so.jx = VOC / 128;
        dim3 grid(VOC / 128, BSZ / BM, 1);
        gemm_f16<false><<<grid, 256>>>(so, Z, Z, VOC, H2);
    }
}

// round 11
// speedup vs baseline: 1.2511x; 1.1745x over previous
#include <cuda_runtime.h>
#include <cuda_fp16.h>
#include <math.h>

// Problem constants
#define BSZ 256
#define SEQ 64
#define HID 512
#define H2  1024
#define H4  2048
#define H8  4096
#define VOC 32000

// ---------------------------------------------------------------------------
// Scratch (no allocations allowed -> __device__ globals)
// ---------------------------------------------------------------------------
__device__ __half g_seq [SEQ * BSZ * HID];
__device__ float  g_gxf [SEQ * BSZ * H4];
__device__ float  g_gxb [SEQ * BSZ * H4];
__device__ float  g_gxc [SEQ * BSZ * H8];
__device__ __half g_comb[SEQ * BSZ * H2];
__device__ __half g_hf[2][BSZ * HID];
__device__ float  g_cf[BSZ * HID];
__device__ __half g_hb[2][BSZ * HID];
__device__ float  g_cb[BSZ * HID];
__device__ __half g_hc[2][BSZ * H2];
__device__ float  g_cc[BSZ * H2];
__device__ __half g_wihf[H4 * HID];
__device__ __half g_whhf[H4 * HID];
__device__ __half g_wihb[H4 * HID];
__device__ __half g_whhb[H4 * HID];
__device__ __half g_wihc[H8 * H2];
__device__ __half g_whhc[H8 * H2];
__device__ __half g_wout[VOC * H2];
__device__ unsigned g_bar;

// ---------------------------------------------------------------------------
// fp32 -> fp16 conversion (4 elems/thread)
// ---------------------------------------------------------------------------
struct __align__(8) Half4 { __half2 a, b; };

__global__ __launch_bounds__(256)
void cvt_kernel(const float4* __restrict__ in, Half4* __restrict__ out, int n4)
{
    int i = blockIdx.x * blockDim.x + threadIdx.x;
    if (i >= n4) return;
    float4 v = in[i];
    Half4 h;
    h.a = __floats2half2_rn(v.x, v.y);
    h.b = __floats2half2_rn(v.z, v.w);
    out[i] = h;
}

// ---------------------------------------------------------------------------
// Embedding gather -> fp16, 4 elems/thread.
// ---------------------------------------------------------------------------
__global__ __launch_bounds__(256)
void embed_kernel(const int* __restrict__ x,
                  const float* __restrict__ W,
                  Half4* __restrict__ seq)
{
    const int H4v = HID / 4;
    int i = blockIdx.x * blockDim.x + threadIdx.x;
    if (i >= BSZ * SEQ * H4v) return;
    int row = i / H4v;
    int h4  = i - row * H4v;
    int idx = x[row];
    float4 v = make_float4(0.f, 0.f, 0.f, 0.f);
    if (idx != 0)
        v = reinterpret_cast<const float4*>(W)[(size_t)idx * H4v + h4];
    Half4 h;
    h.a = __floats2half2_rn(v.x, v.y);
    h.b = __floats2half2_rn(v.z, v.w);
    seq[i] = h;
}

// ---------------------------------------------------------------------------
// Common GEMM plumbing
// ---------------------------------------------------------------------------
#define BM 64
#define BKH 32    // k per tile, halves
#define KSTH 40   // smem k-stride in halves
#define STG 3

#define CP_ASYNC16(dst, src) \
    asm volatile("cp.async.ca.shared.global [%0], [%1], 16;\n" \
                 :: "r"(dst), "l"(src))
#define CP_COMMIT() asm volatile("cp.async.commit_group;\n" ::: "memory")
#define CP_WAIT(n)  asm volatile("cp.async.wait_group %0;\n" :: "n"(n) : "memory")

__device__ __forceinline__ void ldsm4(unsigned& r0, unsigned& r1,
                                      unsigned& r2, unsigned& r3,
                                      unsigned addr)
{
    asm volatile("ldmatrix.sync.aligned.m8n8.x4.shared.b16 {%0,%1,%2,%3}, [%4];"
                 : "=r"(r0), "=r"(r1), "=r"(r2), "=r"(r3) : "r"(addr));
}
__device__ __forceinline__ float sigf(float v) {
    return 1.0f / (1.0f + __expf(-v));
}

#define MMA16816(acc, a, b0v, b1v) \
    asm volatile( \
        "mma.sync.aligned.m16n8k16.row.col.f32.f16.f16.f32 " \
        "{%0,%1,%2,%3}, {%4,%5,%6,%7}, {%8,%9}, {%0,%1,%2,%3};" \
        : "+f"(acc[0]), "+f"(acc[1]), "+f"(acc[2]), "+f"(acc[3]) \
        : "r"(a[0]), "r"(a[1]), "r"(a[2]), "r"(a[3]), "r"(b0v), "r"(b1v))

// ---------------------------------------------------------------------------
// Plain fp16 GEMM (projections / head): C(f32) = A @ W^T [+b0] [+b1]
// 64x128 tile, 8 warps, ldmatrix A+B, 3-stage cp.async.
// ---------------------------------------------------------------------------
struct GemmSet {
    const __half* A;
    const __half* W;     // null => block inactive
    const float*  b0;
    const float*  b1;
    float*        C;
    int           jx;
};

__global__ __launch_bounds__(256)
void gemm_f16(GemmSet s0, GemmSet s1, int N, int K)
{
    GemmSet s = blockIdx.z ? s1 : s0;
    if (s.W == nullptr || (int)blockIdx.x >= s.jx) return;

    __shared__ __half As[STG][BM][KSTH];
    __shared__ __half Bs[STG][128][KSTH];

    const int tid  = threadIdx.x;
    const int lane = tid & 31;
    const int wid  = tid >> 5;
    const int wm   = wid & 1;
    const int wn   = wid >> 1;
    const int m0   = blockIdx.y * BM;
    const int n0   = blockIdx.x * 128;
    const int T    = K / BKH;

    const int a_row = tid >> 2;
    const int a_g   = tid & 3;
    const __half* a_src = s.A + (size_t)(m0 + a_row) * K + a_g * 8;
    int b_g[2];
    const __half* b_src[2];
    unsigned b_dst[2];
#pragma unroll
    for (int p = 0; p < 2; ++p) {
        int idx = tid + 256 * p;
        int row = idx >> 2;
        b_g[p]  = idx & 3;
        b_src[p] = s.W + (size_t)(n0 + row) * K + b_g[p] * 8;
        b_dst[p] = (unsigned)__cvta_generic_to_shared(&Bs[0][row][b_g[p] * 8]);
    }
    unsigned a_dst = (unsigned)__cvta_generic_to_shared(&As[0][a_row][a_g * 8]);
    const unsigned a_stage = BM * KSTH * 2;
    const unsigned b_stage = 128 * KSTH * 2;

    auto load_stage = [&](int st, int kt) {
        CP_ASYNC16(a_dst + st * a_stage, a_src + kt * BKH);
        CP_ASYNC16(b_dst[0] + st * b_stage, b_src[0] + kt * BKH);
        CP_ASYNC16(b_dst[1] + st * b_stage, b_src[1] + kt * BKH);
    };

    const unsigned as_base = (unsigned)__cvta_generic_to_shared(&As[0][0][0]);
    const unsigned bs_base = (unsigned)__cvta_generic_to_shared(&Bs[0][0][0]);

    float acc[2][4][4];
#pragma unroll
    for (int i = 0; i < 2; ++i)
#pragma unroll
        for (int j = 0; j < 4; ++j)
#pragma unroll
            for (int r = 0; r < 4; ++r) acc[i][j][r] = 0.f;

#pragma unroll
    for (int st = 0; st < STG - 1; ++st) {
        if (st < T) load_stage(st, st);
        CP_COMMIT();
    }

    const int lm_rowA = lane & 15;
    const int lm_kA   = (lane >> 4) << 3;
    const int lm_rowB = (lane & 7) + ((lane >> 4) & 1) * 8;
    const int lm_kB   = ((lane >> 3) & 1) * 8;

    for (int kt = 0; kt < T; ++kt) {
        CP_WAIT(STG - 2);
        __syncthreads();
        const int buf = kt % STG;
#pragma unroll
        for (int ks = 0; ks < 2; ++ks) {
            const int c = ks * 16;
            unsigned a[2][4];
#pragma unroll
            for (int mt = 0; mt < 2; ++mt) {
                int r0 = wm * 32 + mt * 16;
                unsigned addr = as_base + (unsigned)buf * a_stage +
                    ((r0 + lm_rowA) * KSTH + c + lm_kA) * 2;
                ldsm4(a[mt][0], a[mt][1], a[mt][2], a[mt][3], addr);
            }
            unsigned bb[2][4];
#pragma unroll
            for (int pr = 0; pr < 2; ++pr) {
                int nb = wn * 32 + pr * 16;
                unsigned addr = bs_base + (unsigned)buf * b_stage +
                    ((nb + lm_rowB) * KSTH + c + lm_kB) * 2;
                ldsm4(bb[pr][0], bb[pr][1], bb[pr][2], bb[pr][3], addr);
            }
#pragma unroll
            for (int nt = 0; nt < 4; ++nt) {
                unsigned bf0 = bb[nt >> 1][(nt & 1) * 2 + 0];
                unsigned bf1 = bb[nt >> 1][(nt & 1) * 2 + 1];
#pragma unroll
                for (int mt = 0; mt < 2; ++mt)
                    MMA16816(acc[mt][nt], a[mt], bf0, bf1);
            }
        }
        const int nk = kt + STG - 1;
        if (nk < T) load_stage(nk % STG, nk);
        CP_COMMIT();
    }

#pragma unroll
    for (int mt = 0; mt < 2; ++mt) {
#pragma unroll
        for (int nt = 0; nt < 4; ++nt) {
            int m = m0 + wm * 32 + mt * 16 + (lane >> 2);
            int n = n0 + wn * 32 + nt * 8 + (lane & 3) * 2;
#pragma unroll
            for (int rr = 0; rr < 2; ++rr) {
                int mm = m + rr * 8;
                size_t off = (size_t)mm * N + n;
                float v0 = acc[mt][nt][rr * 2 + 0];
                float v1 = acc[mt][nt][rr * 2 + 1];
                if (s.b0) { v0 += s.b0[n]; v1 += s.b0[n + 1]; }
                if (s.b1) { v0 += s.b1[n]; v1 += s.b1[n + 1]; }
                *reinterpret_cast<float2*>(s.C + off) = make_float2(v0, v1);
            }
        }
    }
}

// ---------------------------------------------------------------------------
// Persistent LSTM chain: runs nsteps of h' = LSTM(h @ Whh^T + gx) in ONE
// kernel with a device-wide barrier between steps. All blocks are resident
// (128 blocks, 256 thr, 46KB smem on 148 SMs), so the spin barrier is safe.
// Same GEMM core and fused epilogue as before.
// ---------------------------------------------------------------------------
struct ChainSet {
    const __half* W;      // Whh, (4*Hd, Hd) fp16
    const float*  gx;     // input-proj base, slab stride BSZ*4*Hd
    __half*       hb0;    // ping-pong h buffers
    __half*       hb1;
    float*        cbuf;   // fp32 cell state
    __half*       comb;   // optional scatter base (slab stride BSZ*combStride)
    int           combStride;
    int           Hd;
    int           reverse; // 1 => gx slab = nsteps-1-step
};

__global__ __launch_bounds__(256)
void lstm_chain(ChainSet s0, ChainSet s1, int nsteps,
                unsigned* bar, unsigned nblocks)
{
    ChainSet s = blockIdx.z ? s1 : s0;
    const int Hd = s.Hd;
    const int K  = Hd;
    const int T  = K / BKH;

    __shared__ __half As[STG][BM][KSTH];
    __shared__ __half Bs[STG][128][KSTH];

    const int tid  = threadIdx.x;
    const int lane = tid & 31;
    const int wid  = tid >> 5;
    const int wm   = wid & 1;
    const int wn   = wid >> 1;
    const int m0   = blockIdx.y * BM;
    const int n0j  = blockIdx.x * 32;

    // B loader (gate-interleaved rows; constant across steps)
    const int a_row = tid >> 2;
    const int a_g   = tid & 3;
    int b_g[2];
    const __half* b_src[2];
    unsigned b_dst[2];
#pragma unroll
    for (int p = 0; p < 2; ++p) {
        int idx = tid + 256 * p;
        int row = idx >> 2;
        b_g[p]  = idx & 3;
        int wn_r = row >> 5;
        int t    = row & 31;
        int gate = t >> 3;
        int cc   = t & 7;
        int j    = n0j + wn_r * 8 + cc;
        b_src[p] = s.W + (size_t)(gate * Hd + j) * K + b_g[p] * 8;
        b_dst[p] = (unsigned)__cvta_generic_to_shared(&Bs[0][row][b_g[p] * 8]);
    }
    unsigned a_dst = (unsigned)__cvta_generic_to_shared(&As[0][a_row][a_g * 8]);
    const unsigned a_stage = BM * KSTH * 2;
    const unsigned b_stage = 128 * KSTH * 2;
    const unsigned as_base = (unsigned)__cvta_generic_to_shared(&As[0][0][0]);
    const unsigned bs_base = (unsigned)__cvta_generic_to_shared(&Bs[0][0][0]);

    const int lm_rowA = lane & 15;
    const int lm_kA   = (lane >> 4) << 3;
    const int lm_rowB = (lane & 7) + ((lane >> 4) & 1) * 8;
    const int lm_kB   = ((lane >> 3) & 1) * 8;
    const int j = n0j + wn * 8 + (lane & 3) * 2;

    for (int step = 0; step < nsteps; ++step) {
        const __half* hsrc = (step & 1) ? s.hb1 : s.hb0;
        __half*       hdst = (step & 1) ? s.hb0 : s.hb1;
        const int gslab = s.reverse ? (nsteps - 1 - step) : step;
        const float* gxs = s.gx + (size_t)gslab * BSZ * 4 * Hd;
        const __half* a_src = hsrc + (size_t)(m0 + a_row) * K + a_g * 8;

        float acc[2][4][4];
#pragma unroll
        for (int i = 0; i < 2; ++i)
#pragma unroll
            for (int q = 0; q < 4; ++q)
#pragma unroll
                for (int r = 0; r < 4; ++r) acc[i][q][r] = 0.f;

        // pipeline prologue
#pragma unroll
        for (int st = 0; st < STG - 1; ++st) {
            if (st < T) {
                CP_ASYNC16(a_dst + st * a_stage, a_src + st * BKH);
                CP_ASYNC16(b_dst[0] + st * b_stage, b_src[0] + st * BKH);
                CP_ASYNC16(b_dst[1] + st * b_stage, b_src[1] + st * BKH);
            }
            CP_COMMIT();
        }

        for (int kt = 0; kt < T; ++kt) {
            CP_WAIT(STG - 2);
            __syncthreads();
            const int buf = kt % STG;
#pragma unroll
            for (int ks = 0; ks < 2; ++ks) {
                const int c = ks * 16;
                unsigned a[2][4];
#pragma unroll
                for (int mt = 0; mt < 2; ++mt) {
                    int r0 = wm * 32 + mt * 16;
                    unsigned addr = as_base + (unsigned)buf * a_stage +
                        ((r0 + lm_rowA) * KSTH + c + lm_kA) * 2;
                    ldsm4(a[mt][0], a[mt][1], a[mt][2], a[mt][3], addr);
                }
                unsigned bb[2][4];
#pragma unroll
                for (int pr = 0; pr < 2; ++pr) {
                    int nb = wn * 32 + pr * 16;
                    unsigned addr = bs_base + (unsigned)buf * b_stage +
                        ((nb + lm_rowB) * KSTH + c + lm_kB) * 2;
                    ldsm4(bb[pr][0], bb[pr][1], bb[pr][2], bb[pr][3], addr);
                }
#pragma unroll
                for (int nt = 0; nt < 4; ++nt) {
                    unsigned bf0 = bb[nt >> 1][(nt & 1) * 2 + 0];
                    unsigned bf1 = bb[nt >> 1][(nt & 1) * 2 + 1];
#pragma unroll
                    for (int mt = 0; mt < 2; ++mt)
                        MMA16816(acc[mt][nt], a[mt], bf0, bf1);
                }
            }
            const int nk = kt + STG - 1;
            if (nk < T) {
                const int st = nk % STG;
                CP_ASYNC16(a_dst + st * a_stage, a_src + nk * BKH);
                CP_ASYNC16(b_dst[0] + st * b_stage, b_src[0] + nk * BKH);
                CP_ASYNC16(b_dst[1] + st * b_stage, b_src[1] + nk * BKH);
            }
            CP_COMMIT();
        }

        // fused LSTM epilogue
#pragma unroll
        for (int mt = 0; mt < 2; ++mt) {
#pragma unroll
            for (int rr = 0; rr < 2; ++rr) {
                int m = m0 + wm * 32 + mt * 16 + (lane >> 2) + rr * 8;
                const float* gx = gxs + (size_t)m * 4 * Hd;
                float2 di = *reinterpret_cast<const float2*>(gx +          j);
                float2 df = *reinterpret_cast<const float2*>(gx +     Hd + j);
                float2 dg = *reinterpret_cast<const float2*>(gx + 2 * Hd + j);
                float2 do_= *reinterpret_cast<const float2*>(gx + 3 * Hd + j);
                float2 cv = *reinterpret_cast<const float2*>(
                    s.cbuf + (size_t)m * Hd + j);

                float pi0 = acc[mt][0][rr * 2 + 0] + di.x;
                float pi1 = acc[mt][0][rr * 2 + 1] + di.y;
                float pf0 = acc[mt][1][rr * 2 + 0] + df.x;
                float pf1 = acc[mt][1][rr * 2 + 1] + df.y;
                float pg0 = acc[mt][2][rr * 2 + 0] + dg.x;
                float pg1 = acc[mt][2][rr * 2 + 1] + dg.y;
                float po0 = acc[mt][3][rr * 2 + 0] + do_.x;
                float po1 = acc[mt][3][rr * 2 + 1] + do_.y;

                float cn0 = sigf(pf0) * cv.x + sigf(pi0) * tanhf(pg0);
                float cn1 = sigf(pf1) * cv.y + sigf(pi1) * tanhf(pg1);
                float hn0 = sigf(po0) * tanhf(cn0);
                float hn1 = sigf(po1) * tanhf(cn1);

                *reinterpret_cast<float2*>(s.cbuf + (size_t)m * Hd + j) =
                    make_float2(cn0, cn1);
                __half2 hh = __floats2half2_rn(hn0, hn1);
                *reinterpret_cast<__half2*>(hdst + (size_t)m * Hd + j) = hh;
                if (s.comb)
                    *reinterpret_cast<__half2*>(
                        s.comb + (size_t)step * BSZ * s.combStride +
                        (size_t)m * s.combStride + j) = hh;
            }
        }

        // device-wide barrier between steps (skipped after last step)
        if (step + 1 < nsteps) {
            __syncthreads();
            if (tid == 0) {
                __threadfence();
                atomicAdd(bar, 1u);
                unsigned target = (unsigned)(step + 1) * nblocks;
                unsigned v;
                do {
                    asm volatile("ld.acquire.gpu.global.u32 %0, [%1];"
                                 : "=r"(v) : "l"(bar) : "memory");
                } while (v < target);
            }
            __syncthreads();
        }
    }
}

// ---------------------------------------------------------------------------
// kernel_launch
// ---------------------------------------------------------------------------
extern "C" void kernel_launch(void* const* d_in, const int* in_sizes, int n_in,
                              void* d_out, int out_size)
{
    const int*   x     = (const int*)  d_in[0];
    const float* W_emb = (const float*)d_in[1];
    const float* Wih_f = (const float*)d_in[2];
    const float* Whh_f = (const float*)d_in[3];
    const float* bih_f = (const float*)d_in[4];
    const float* bhh_f = (const float*)d_in[5];
    const float* Wih_b = (const float*)d_in[6];
    const float* Whh_b = (const float*)d_in[7];
    const float* bih_b = (const float*)d_in[8];
    const float* bhh_b = (const float*)d_in[9];
    const float* Wih_c = (const float*)d_in[10];
    const float* Whh_c = (const float*)d_in[11];
    const float* bih_c = (const float*)d_in[12];
    const float* bhh_c = (const float*)d_in[13];
    const float* Wout  = (const float*)d_in[14];
    const float* bout  = (const float*)d_in[15];
    const float* h0f   = (const float*)d_in[16];
    const float* c0f   = (const float*)d_in[17];
    const float* h0b   = (const float*)d_in[18];
    const float* c0b   = (const float*)d_in[19];
    const float* h0c   = (const float*)d_in[20];
    const float* c0c   = (const float*)d_in[21];
    float* out = (float*)d_out;

    __half *seq, *comb, *hf, *hb, *hc;
    __half *wihf, *whhf, *wihb, *whhb, *wihc, *whhc, *wout;
    float *gxf, *gxb, *gxc, *cf, *cb, *cc;
    unsigned* bar;
    cudaGetSymbolAddress((void**)&seq,  g_seq);
    cudaGetSymbolAddress((void**)&gxf,  g_gxf);
    cudaGetSymbolAddress((void**)&gxb,  g_gxb);
    cudaGetSymbolAddress((void**)&gxc,  g_gxc);
    cudaGetSymbolAddress((void**)&comb, g_comb);
    cudaGetSymbolAddress((void**)&hf,   g_hf);
    cudaGetSymbolAddress((void**)&cf,   g_cf);
    cudaGetSymbolAddress((void**)&hb,   g_hb);
    cudaGetSymbolAddress((void**)&cb,   g_cb);
    cudaGetSymbolAddress((void**)&hc,   g_hc);
    cudaGetSymbolAddress((void**)&cc,   g_cc);
    cudaGetSymbolAddress((void**)&wihf, g_wihf);
    cudaGetSymbolAddress((void**)&whhf, g_whhf);
    cudaGetSymbolAddress((void**)&wihb, g_wihb);
    cudaGetSymbolAddress((void**)&whhb, g_whhb);
    cudaGetSymbolAddress((void**)&wihc, g_wihc);
    cudaGetSymbolAddress((void**)&whhc, g_whhc);
    cudaGetSymbolAddress((void**)&wout, g_wout);
    cudaGetSymbolAddress((void**)&bar,  g_bar);

    __half* hfb[2] = {hf, hf + BSZ * HID};
    __half* hbb[2] = {hb, hb + BSZ * HID};
    __half* hcb[2] = {hc, hc + BSZ * H2};

    auto cvt = [](const float* in, __half* out_, int n) {
        int n4 = n / 4;
        cvt_kernel<<<(n4 + 255) / 256, 256>>>(
            (const float4*)in, (Half4*)out_, n4);
    };

    cvt(Wih_f, wihf, H4 * HID);
    cvt(Whh_f, whhf, H4 * HID);
    cvt(Wih_b, wihb, H4 * HID);
    cvt(Whh_b, whhb, H4 * HID);
    cvt(Wih_c, wihc, H8 * H2);
    cvt(Whh_c, whhc, H8 * H2);
    cvt(Wout,  wout, VOC * H2);
    cvt(h0f, hfb[0], BSZ * HID);
    cvt(h0b, hbb[0], BSZ * HID);
    cvt(h0c, hcb[0], BSZ * H2);

    cudaMemcpyAsync(cf, c0f, BSZ * HID * sizeof(float), cudaMemcpyDeviceToDevice, 0);
    cudaMemcpyAsync(cb, c0b, BSZ * HID * sizeof(float), cudaMemcpyDeviceToDevice, 0);
    cudaMemcpyAsync(cc, c0c, BSZ * H2  * sizeof(float), cudaMemcpyDeviceToDevice, 0);

    {
        int total4 = BSZ * SEQ * (HID / 4);
        embed_kernel<<<(total4 + 255) / 256, 256>>>(x, W_emb, (Half4*)seq);
    }

    GemmSet Z = {};

    // Batched input projections for f and b cells
    {
        GemmSet sf = Z;
        sf.A = seq; sf.W = wihf; sf.b0 = bih_f; sf.b1 = bhh_f; sf.C = gxf;
        sf.jx = H4 / 128;
        GemmSet sb = sf;
        sb.W = wihb; sb.b0 = bih_b; sb.b1 = bhh_b; sb.C = gxb;
        dim3 grid(H4 / 128, (SEQ * BSZ) / BM, 2);
        gemm_f16<<<grid, 256>>>(sf, sb, H4, HID);
    }

    // Persistent f/b recurrence chain (ONE launch, 64 steps)
    {
        cudaMemsetAsync(bar, 0, sizeof(unsigned), 0);
        ChainSet f = {};
        f.W = whhf; f.gx = gxf; f.hb0 = hfb[0]; f.hb1 = hfb[1];
        f.cbuf = cf; f.comb = comb; f.combStride = H2;
        f.Hd = HID; f.reverse = 0;
        ChainSet b = f;
        b.W = whhb; b.gx = gxb; b.hb0 = hbb[0]; b.hb1 = hbb[1];
        b.cbuf = cb; b.comb = comb + HID; b.reverse = 1;
        dim3 grid(HID / 32, BSZ / BM, 2);   // 16*4*2 = 128 blocks, all resident
        lstm_chain<<<grid, 256>>>(f, b, SEQ, bar, 128u);
    }

    // Batched input projection for combiner cell
    {
        GemmSet sc = Z;
        sc.A = comb; sc.W = wihc; sc.b0 = bih_c; sc.b1 = bhh_c; sc.C = gxc;
        sc.jx = H8 / 128;
        dim3 grid(H8 / 128, (SEQ * BSZ) / BM, 1);
        gemm_f16<<<grid, 256>>>(sc, Z, H8, H2);
    }

    // Persistent combiner recurrence chain (ONE launch, 64 steps)
    {
        cudaMemsetAsync(bar, 0, sizeof(unsigned), 0);
        ChainSet c = {};
        c.W = whhc; c.gx = gxc; c.hb0 = hcb[0]; c.hb1 = hcb[1];
        c.cbuf = cc; c.comb = nullptr; c.combStride = 0;
        c.Hd = H2; c.reverse = 0;
        dim3 grid(H2 / 32, BSZ / BM, 1);    // 32*4 = 128 blocks, all resident
        lstm_chain<<<grid, 256>>>(c, c, SEQ, bar, 128u);
    }

    // output head: out = hc_final @ Wout^T + bout (SEQ even -> final in buf 0)
    {
        GemmSet so = Z;
        so.A = hcb[0]; so.W = wout; so.b0 = bout; so.C = out;
        so.jx = VOC / 128;
        dim3 grid(VOC / 128, BSZ / BM, 1);
        gemm_f16<<<grid, 256>>>(so, Z, VOC, H2);
    }
}

// round 13
// speedup vs baseline: 1.2559x; 1.0039x over previous
#include <cuda_runtime.h>
#include <cuda_fp16.h>
#include <math.h>

// Problem constants
#define BSZ 256
#define SEQ 64
#define HID 512
#define H2  1024
#define H4  2048
#define H8  4096
#define VOC 32000

// ---------------------------------------------------------------------------
// Scratch (no allocations allowed -> __device__ globals)
// ---------------------------------------------------------------------------
__device__ __half g_seq [SEQ * BSZ * HID];
__device__ __half g_gxf [SEQ * BSZ * H4];     // fp16 input projections
__device__ __half g_gxb [SEQ * BSZ * H4];
__device__ __half g_gxc [SEQ * BSZ * H8];
__device__ __half g_comb[SEQ * BSZ * H2];
__device__ __half g_hf[2][BSZ * HID];
__device__ float  g_cf[BSZ * HID];
__device__ __half g_hb[2][BSZ * HID];
__device__ float  g_cb[BSZ * HID];
__device__ __half g_hc[2][BSZ * H2];
__device__ float  g_cc[BSZ * H2];
__device__ __half g_wihf[H4 * HID];
__device__ __half g_whhf[H4 * HID];
__device__ __half g_wihb[H4 * HID];
__device__ __half g_whhb[H4 * HID];
__device__ __half g_wihc[H8 * H2];
__device__ __half g_whhc[H8 * H2];
__device__ unsigned g_bar;

// ---------------------------------------------------------------------------
// fp32 -> fp16 conversion (4 elems/thread)
// ---------------------------------------------------------------------------
struct __align__(8) Half4 { __half2 a, b; };

__global__ __launch_bounds__(256)
void cvt_kernel(const float4* __restrict__ in, Half4* __restrict__ out, int n4)
{
    int i = blockIdx.x * blockDim.x + threadIdx.x;
    if (i >= n4) return;
    float4 v = in[i];
    Half4 h;
    h.a = __floats2half2_rn(v.x, v.y);
    h.b = __floats2half2_rn(v.z, v.w);
    out[i] = h;
}

// ---------------------------------------------------------------------------
// Embedding gather -> fp16, 4 elems/thread.
// ---------------------------------------------------------------------------
__global__ __launch_bounds__(256)
void embed_kernel(const int* __restrict__ x,
                  const float* __restrict__ W,
                  Half4* __restrict__ seq)
{
    const int H4v = HID / 4;
    int i = blockIdx.x * blockDim.x + threadIdx.x;
    if (i >= BSZ * SEQ * H4v) return;
    int row = i / H4v;
    int h4  = i - row * H4v;
    int idx = x[row];
    float4 v = make_float4(0.f, 0.f, 0.f, 0.f);
    if (idx != 0)
        v = reinterpret_cast<const float4*>(W)[(size_t)idx * H4v + h4];
    Half4 h;
    h.a = __floats2half2_rn(v.x, v.y);
    h.b = __floats2half2_rn(v.z, v.w);
    seq[i] = h;
}

// ---------------------------------------------------------------------------
// Common GEMM plumbing
// ---------------------------------------------------------------------------
#define BM 64
#define BKH 32    // k per tile, halves
#define KSTH 40   // smem k-stride in halves
#define STG 3

#define CP_ASYNC16(dst, src) \
    asm volatile("cp.async.ca.shared.global [%0], [%1], 16;\n" \
                 :: "r"(dst), "l"(src))
#define CP_COMMIT() asm volatile("cp.async.commit_group;\n" ::: "memory")
#define CP_WAIT(n)  asm volatile("cp.async.wait_group %0;\n" :: "n"(n) : "memory")

__device__ __forceinline__ void ldsm4(unsigned& r0, unsigned& r1,
                                      unsigned& r2, unsigned& r3,
                                      unsigned addr)
{
    asm volatile("ldmatrix.sync.aligned.m8n8.x4.shared.b16 {%0,%1,%2,%3}, [%4];"
                 : "=r"(r0), "=r"(r1), "=r"(r2), "=r"(r3) : "r"(addr));
}
__device__ __forceinline__ float sigf(float v) {
    return 1.0f / (1.0f + __expf(-v));
}

#define MMA16816(acc, a, b0v, b1v) \
    asm volatile( \
        "mma.sync.aligned.m16n8k16.row.col.f32.f16.f16.f32 " \
        "{%0,%1,%2,%3}, {%4,%5,%6,%7}, {%8,%9}, {%0,%1,%2,%3};" \
        : "+f"(acc[0]), "+f"(acc[1]), "+f"(acc[2]), "+f"(acc[3]) \
        : "r"(a[0]), "r"(a[1]), "r"(a[2]), "r"(a[3]), "r"(b0v), "r"(b1v))

// ---------------------------------------------------------------------------
// Plain fp16 GEMM (input projections): C(fp16) = A @ W^T + b0 + b1
// 64x128 tile, 8 warps, ldmatrix A+B, 3-stage cp.async.
// ---------------------------------------------------------------------------
struct GemmSet {
    const __half* A;
    const __half* W;     // null => block inactive
    const float*  b0;
    const float*  b1;
    __half*       C;
    int           jx;
};

__global__ __launch_bounds__(256)
void gemm_f16(GemmSet s0, GemmSet s1, int N, int K)
{
    GemmSet s = blockIdx.z ? s1 : s0;
    if (s.W == nullptr || (int)blockIdx.x >= s.jx) return;

    __shared__ __half As[STG][BM][KSTH];
    __shared__ __half Bs[STG][128][KSTH];

    const int tid  = threadIdx.x;
    const int lane = tid & 31;
    const int wid  = tid >> 5;
    const int wm   = wid & 1;
    const int wn   = wid >> 1;
    const int m0   = blockIdx.y * BM;
    const int n0   = blockIdx.x * 128;
    const int T    = K / BKH;

    const int a_row = tid >> 2;
    const int a_g   = tid & 3;
    const __half* a_src = s.A + (size_t)(m0 + a_row) * K + a_g * 8;
    int b_g[2];
    const __half* b_src[2];
    unsigned b_dst[2];
#pragma unroll
    for (int p = 0; p < 2; ++p) {
        int idx = tid + 256 * p;
        int row = idx >> 2;
        b_g[p]  = idx & 3;
        b_src[p] = s.W + (size_t)(n0 + row) * K + b_g[p] * 8;
        b_dst[p] = (unsigned)__cvta_generic_to_shared(&Bs[0][row][b_g[p] * 8]);
    }
    unsigned a_dst = (unsigned)__cvta_generic_to_shared(&As[0][a_row][a_g * 8]);
    const unsigned a_stage = BM * KSTH * 2;
    const unsigned b_stage = 128 * KSTH * 2;

    auto load_stage = [&](int st, int kt) {
        CP_ASYNC16(a_dst + st * a_stage, a_src + kt * BKH);
        CP_ASYNC16(b_dst[0] + st * b_stage, b_src[0] + kt * BKH);
        CP_ASYNC16(b_dst[1] + st * b_stage, b_src[1] + kt * BKH);
    };

    const unsigned as_base = (unsigned)__cvta_generic_to_shared(&As[0][0][0]);
    const unsigned bs_base = (unsigned)__cvta_generic_to_shared(&Bs[0][0][0]);

    float acc[2][4][4];
#pragma unroll
    for (int i = 0; i < 2; ++i)
#pragma unroll
        for (int j = 0; j < 4; ++j)
#pragma unroll
            for (int r = 0; r < 4; ++r) acc[i][j][r] = 0.f;

#pragma unroll
    for (int st = 0; st < STG - 1; ++st) {
        if (st < T) load_stage(st, st);
        CP_COMMIT();
    }

    const int lm_rowA = lane & 15;
    const int lm_kA   = (lane >> 4) << 3;
    const int lm_rowB = (lane & 7) + ((lane >> 4) & 1) * 8;
    const int lm_kB   = ((lane >> 3) & 1) * 8;

    for (int kt = 0; kt < T; ++kt) {
        CP_WAIT(STG - 2);
        __syncthreads();
        const int buf = kt % STG;
#pragma unroll
        for (int ks = 0; ks < 2; ++ks) {
            const int c = ks * 16;
            unsigned a[2][4];
#pragma unroll
            for (int mt = 0; mt < 2; ++mt) {
                int r0 = wm * 32 + mt * 16;
                unsigned addr = as_base + (unsigned)buf * a_stage +
                    ((r0 + lm_rowA) * KSTH + c + lm_kA) * 2;
                ldsm4(a[mt][0], a[mt][1], a[mt][2], a[mt][3], addr);
            }
            unsigned bb[2][4];
#pragma unroll
            for (int pr = 0; pr < 2; ++pr) {
                int nb = wn * 32 + pr * 16;
                unsigned addr = bs_base + (unsigned)buf * b_stage +
                    ((nb + lm_rowB) * KSTH + c + lm_kB) * 2;
                ldsm4(bb[pr][0], bb[pr][1], bb[pr][2], bb[pr][3], addr);
            }
#pragma unroll
            for (int nt = 0; nt < 4; ++nt) {
                unsigned bf0 = bb[nt >> 1][(nt & 1) * 2 + 0];
                unsigned bf1 = bb[nt >> 1][(nt & 1) * 2 + 1];
#pragma unroll
                for (int mt = 0; mt < 2; ++mt)
                    MMA16816(acc[mt][nt], a[mt], bf0, bf1);
            }
        }
        const int nk = kt + STG - 1;
        if (nk < T) load_stage(nk % STG, nk);
        CP_COMMIT();
    }

#pragma unroll
    for (int mt = 0; mt < 2; ++mt) {
#pragma unroll
        for (int nt = 0; nt < 4; ++nt) {
            int m = m0 + wm * 32 + mt * 16 + (lane >> 2);
            int n = n0 + wn * 32 + nt * 8 + (lane & 3) * 2;
#pragma unroll
            for (int rr = 0; rr < 2; ++rr) {
                int mm = m + rr * 8;
                size_t off = (size_t)mm * N + n;
                float v0 = acc[mt][nt][rr * 2 + 0];
                float v1 = acc[mt][nt][rr * 2 + 1];
                v0 += s.b0[n] + s.b1[n];
                v1 += s.b0[n + 1] + s.b1[n + 1];
                *reinterpret_cast<__half2*>(s.C + off) =
                    __floats2half2_rn(v0, v1);
            }
        }
    }
}

// ---------------------------------------------------------------------------
// Head GEMM: out(f32) = A(fp16) @ Wf32^T + bias. Reads fp32 weights
// directly (register-staged LDG->cvt->STS, 2-stage), avoiding the separate
// 192MB convert pass. A-side identical fp16 path via register staging too.
// ---------------------------------------------------------------------------
__global__ __launch_bounds__(256)
void gemm_head(const __half* __restrict__ A, const float* __restrict__ W,
               const float* __restrict__ bias, float* __restrict__ C,
               int N, int K)
{
    __shared__ __half As[2][BM][KSTH];
    __shared__ __half Bs[2][128][KSTH];

    const int tid  = threadIdx.x;
    const int lane = tid & 31;
    const int wid  = tid >> 5;
    const int wm   = wid & 1;
    const int wn   = wid >> 1;
    const int m0   = blockIdx.y * BM;
    const int n0   = blockIdx.x * 128;
    const int T    = K / BKH;

    // A: 64 rows x 4 granules of 8 halves
    const int a_row = tid >> 2;
    const int a_g   = tid & 3;
    const __half* a_src = A + (size_t)(m0 + a_row) * K + a_g * 8;
    // B: 128 rows x 8 float4 per row = 1024 chunks; 4 per thread
    int b_row[4], b_q[4];
    const float* b_src[4];
#pragma unroll
    for (int p = 0; p < 4; ++p) {
        int idx = tid + 256 * p;
        b_row[p] = idx >> 3;
        b_q[p]   = idx & 7;
        b_src[p] = W + (size_t)(n0 + b_row[p]) * K + b_q[p] * 4;
    }

    uint4  aR;
    float4 bR[4];
    auto ldg_tile = [&](int kt) {
        aR = *reinterpret_cast<const uint4*>(a_src + kt * BKH);
#pragma unroll
        for (int p = 0; p < 4; ++p)
            bR[p] = *reinterpret_cast<const float4*>(b_src[p] + kt * BKH);
    };
    auto sts_tile = [&](int buf) {
        *reinterpret_cast<uint4*>(&As[buf][a_row][a_g * 8]) = aR;
#pragma unroll
        for (int p = 0; p < 4; ++p) {
            __half2 h0 = __floats2half2_rn(bR[p].x, bR[p].y);
            __half2 h1 = __floats2half2_rn(bR[p].z, bR[p].w);
            __half2* dst = reinterpret_cast<__half2*>(
                &Bs[buf][b_row[p]][b_q[p] * 4]);
            dst[0] = h0;
            dst[1] = h1;
        }
    };

    const unsigned a_stage = BM * KSTH * 2;
    const unsigned b_stage = 128 * KSTH * 2;
    const unsigned as_base = (unsigned)__cvta_generic_to_shared(&As[0][0][0]);
    const unsigned bs_base = (unsigned)__cvta_generic_to_shared(&Bs[0][0][0]);

    float acc[2][4][4];
#pragma unroll
    for (int i = 0; i < 2; ++i)
#pragma unroll
        for (int j = 0; j < 4; ++j)
#pragma unroll
            for (int r = 0; r < 4; ++r) acc[i][j][r] = 0.f;

    ldg_tile(0);
    sts_tile(0);
    __syncthreads();

    const int lm_rowA = lane & 15;
    const int lm_kA   = (lane >> 4) << 3;
    const int lm_rowB = (lane & 7) + ((lane >> 4) & 1) * 8;
    const int lm_kB   = ((lane >> 3) & 1) * 8;

    for (int kt = 0; kt < T; ++kt) {
        if (kt + 1 < T) ldg_tile(kt + 1);
        const int buf = kt & 1;
#pragma unroll
        for (int ks = 0; ks < 2; ++ks) {
            const int c = ks * 16;
            unsigned a[2][4];
#pragma unroll
            for (int mt = 0; mt < 2; ++mt) {
                int r0 = wm * 32 + mt * 16;
                unsigned addr = as_base + (unsigned)buf * a_stage +
                    ((r0 + lm_rowA) * KSTH + c + lm_kA) * 2;
                ldsm4(a[mt][0], a[mt][1], a[mt][2], a[mt][3], addr);
            }
            unsigned bb[2][4];
#pragma unroll
            for (int pr = 0; pr < 2; ++pr) {
                int nb = wn * 32 + pr * 16;
                unsigned addr = bs_base + (unsigned)buf * b_stage +
                    ((nb + lm_rowB) * KSTH + c + lm_kB) * 2;
                ldsm4(bb[pr][0], bb[pr][1], bb[pr][2], bb[pr][3], addr);
            }
#pragma unroll
            for (int nt = 0; nt < 4; ++nt) {
                unsigned bf0 = bb[nt >> 1][(nt & 1) * 2 + 0];
                unsigned bf1 = bb[nt >> 1][(nt & 1) * 2 + 1];
#pragma unroll
                for (int mt = 0; mt < 2; ++mt)
                    MMA16816(acc[mt][nt], a[mt], bf0, bf1);
            }
        }
        if (kt + 1 < T) {
            sts_tile((kt + 1) & 1);
            __syncthreads();
        }
    }

#pragma unroll
    for (int mt = 0; mt < 2; ++mt) {
#pragma unroll
        for (int nt = 0; nt < 4; ++nt) {
            int m = m0 + wm * 32 + mt * 16 + (lane >> 2);
            int n = n0 + wn * 32 + nt * 8 + (lane & 3) * 2;
#pragma unroll
            for (int rr = 0; rr < 2; ++rr) {
                int mm = m + rr * 8;
                size_t off = (size_t)mm * N + n;
                float v0 = acc[mt][nt][rr * 2 + 0] + bias[n];
                float v1 = acc[mt][nt][rr * 2 + 1] + bias[n + 1];
                *reinterpret_cast<float2*>(C + off) = make_float2(v0, v1);
            }
        }
    }
}

// ---------------------------------------------------------------------------
// Persistent LSTM chain: nsteps of h' = LSTM(h @ Whh^T + gx) in ONE kernel
// with a device-wide barrier between steps (128 resident blocks).
// ---------------------------------------------------------------------------
struct ChainSet {
    const __half* W;      // Whh, (4*Hd, Hd) fp16
    const __half* gx;     // fp16 input-proj base, slab stride BSZ*4*Hd
    __half*       hb0;
    __half*       hb1;
    float*        cbuf;
    __half*       comb;
    int           combStride;
    int           Hd;
    int           reverse;
};

__global__ __launch_bounds__(256)
void lstm_chain(ChainSet s0, ChainSet s1, int nsteps,
                unsigned* bar, unsigned nblocks)
{
    ChainSet s = blockIdx.z ? s1 : s0;
    const int Hd = s.Hd;
    const int K  = Hd;
    const int T  = K / BKH;

    __shared__ __half As[STG][BM][KSTH];
    __shared__ __half Bs[STG][128][KSTH];

    const int tid  = threadIdx.x;
    const int lane = tid & 31;
    const int wid  = tid >> 5;
    const int wm   = wid & 1;
    const int wn   = wid >> 1;
    const int m0   = blockIdx.y * BM;
    const int n0j  = blockIdx.x * 32;

    const int a_row = tid >> 2;
    const int a_g   = tid & 3;
    int b_g[2];
    const __half* b_src[2];
    unsigned b_dst[2];
#pragma unroll
    for (int p = 0; p < 2; ++p) {
        int idx = tid + 256 * p;
        int row = idx >> 2;
        b_g[p]  = idx & 3;
        int wn_r = row >> 5;
        int t    = row & 31;
        int gate = t >> 3;
        int cc   = t & 7;
        int j    = n0j + wn_r * 8 + cc;
        b_src[p] = s.W + (size_t)(gate * Hd + j) * K + b_g[p] * 8;
        b_dst[p] = (unsigned)__cvta_generic_to_shared(&Bs[0][row][b_g[p] * 8]);
    }
    unsigned a_dst = (unsigned)__cvta_generic_to_shared(&As[0][a_row][a_g * 8]);
    const unsigned a_stage = BM * KSTH * 2;
    const unsigned b_stage = 128 * KSTH * 2;
    const unsigned as_base = (unsigned)__cvta_generic_to_shared(&As[0][0][0]);
    const unsigned bs_base = (unsigned)__cvta_generic_to_shared(&Bs[0][0][0]);

    const int lm_rowA = lane & 15;
    const int lm_kA   = (lane >> 4) << 3;
    const int lm_rowB = (lane & 7) + ((lane >> 4) & 1) * 8;
    const int lm_kB   = ((lane >> 3) & 1) * 8;
    const int j = n0j + wn * 8 + (lane & 3) * 2;

    for (int step = 0; step < nsteps; ++step) {
        const __half* hsrc = (step & 1) ? s.hb1 : s.hb0;
        __half*       hdst = (step & 1) ? s.hb0 : s.hb1;
        const int gslab = s.reverse ? (nsteps - 1 - step) : step;
        const __half* gxs = s.gx + (size_t)gslab * BSZ * 4 * Hd;
        const __half* a_src = hsrc + (size_t)(m0 + a_row) * K + a_g * 8;

        float acc[2][4][4];
#pragma unroll
        for (int i = 0; i < 2; ++i)
#pragma unroll
            for (int q = 0; q < 4; ++q)
#pragma unroll
                for (int r = 0; r < 4; ++r) acc[i][q][r] = 0.f;

#pragma unroll
        for (int st = 0; st < STG - 1; ++st) {
            if (st < T) {
                CP_ASYNC16(a_dst + st * a_stage, a_src + st * BKH);
                CP_ASYNC16(b_dst[0] + st * b_stage, b_src[0] + st * BKH);
                CP_ASYNC16(b_dst[1] + st * b_stage, b_src[1] + st * BKH);
            }
            CP_COMMIT();
        }

        for (int kt = 0; kt < T; ++kt) {
            CP_WAIT(STG - 2);
            __syncthreads();
            const int buf = kt % STG;
#pragma unroll
            for (int ks = 0; ks < 2; ++ks) {
                const int c = ks * 16;
                unsigned a[2][4];
#pragma unroll
                for (int mt = 0; mt < 2; ++mt) {
                    int r0 = wm * 32 + mt * 16;
                    unsigned addr = as_base + (unsigned)buf * a_stage +
                        ((r0 + lm_rowA) * KSTH + c + lm_kA) * 2;
                    ldsm4(a[mt][0], a[mt][1], a[mt][2], a[mt][3], addr);
                }
                unsigned bb[2][4];
#pragma unroll
                for (int pr = 0; pr < 2; ++pr) {
                    int nb = wn * 32 + pr * 16;
                    unsigned addr = bs_base + (unsigned)buf * b_stage +
                        ((nb + lm_rowB) * KSTH + c + lm_kB) * 2;
                    ldsm4(bb[pr][0], bb[pr][1], bb[pr][2], bb[pr][3], addr);
                }
#pragma unroll
                for (int nt = 0; nt < 4; ++nt) {
                    unsigned bf0 = bb[nt >> 1][(nt & 1) * 2 + 0];
                    unsigned bf1 = bb[nt >> 1][(nt & 1) * 2 + 1];
#pragma unroll
                    for (int mt = 0; mt < 2; ++mt)
                        MMA16816(acc[mt][nt], a[mt], bf0, bf1);
                }
            }
            const int nk = kt + STG - 1;
            if (nk < T) {
                const int st = nk % STG;
                CP_ASYNC16(a_dst + st * a_stage, a_src + nk * BKH);
                CP_ASYNC16(b_dst[0] + st * b_stage, b_src[0] + nk * BKH);
                CP_ASYNC16(b_dst[1] + st * b_stage, b_src[1] + nk * BKH);
            }
            CP_COMMIT();
        }

        // fused LSTM epilogue (gx is fp16 now)
#pragma unroll
        for (int mt = 0; mt < 2; ++mt) {
#pragma unroll
            for (int rr = 0; rr < 2; ++rr) {
                int m = m0 + wm * 32 + mt * 16 + (lane >> 2) + rr * 8;
                const __half* gx = gxs + (size_t)m * 4 * Hd;
                float2 di = __half22float2(
                    *reinterpret_cast<const __half2*>(gx +          j));
                float2 df = __half22float2(
                    *reinterpret_cast<const __half2*>(gx +     Hd + j));
                float2 dg = __half22float2(
                    *reinterpret_cast<const __half2*>(gx + 2 * Hd + j));
                float2 do_= __half22float2(
                    *reinterpret_cast<const __half2*>(gx + 3 * Hd + j));
                float2 cv = *reinterpret_cast<const float2*>(
                    s.cbuf + (size_t)m * Hd + j);

                float pi0 = acc[mt][0][rr * 2 + 0] + di.x;
                float pi1 = acc[mt][0][rr * 2 + 1] + di.y;
                float pf0 = acc[mt][1][rr * 2 + 0] + df.x;
                float pf1 = acc[mt][1][rr * 2 + 1] + df.y;
                float pg0 = acc[mt][2][rr * 2 + 0] + dg.x;
                float pg1 = acc[mt][2][rr * 2 + 1] + dg.y;
                float po0 = acc[mt][3][rr * 2 + 0] + do_.x;
                float po1 = acc[mt][3][rr * 2 + 1] + do_.y;

                float cn0 = sigf(pf0) * cv.x + sigf(pi0) * tanhf(pg0);
                float cn1 = sigf(pf1) * cv.y + sigf(pi1) * tanhf(pg1);
                float hn0 = sigf(po0) * tanhf(cn0);
                float hn1 = sigf(po1) * tanhf(cn1);

                *reinterpret_cast<float2*>(s.cbuf + (size_t)m * Hd + j) =
                    make_float2(cn0, cn1);
                __half2 hh = __floats2half2_rn(hn0, hn1);
                *reinterpret_cast<__half2*>(hdst + (size_t)m * Hd + j) = hh;
                if (s.comb)
                    *reinterpret_cast<__half2*>(
                        s.comb + (size_t)step * BSZ * s.combStride +
                        (size_t)m * s.combStride + j) = hh;
            }
        }

        if (step + 1 < nsteps) {
            __syncthreads();
            if (tid == 0) {
                __threadfence();
                atomicAdd(bar, 1u);
                unsigned target = (unsigned)(step + 1) * nblocks;
                unsigned v;
                do {
                    asm volatile("ld.acquire.gpu.global.u32 %0, [%1];"
                                 : "=r"(v) : "l"(bar) : "memory");
                } while (v < target);
            }
            __syncthreads();
        }
    }
}

// ---------------------------------------------------------------------------
// kernel_launch
// ---------------------------------------------------------------------------
extern "C" void kernel_launch(void* const* d_in, const int* in_sizes, int n_in,
                              void* d_out, int out_size)
{
    const int*   x     = (const int*)  d_in[0];
    const float* W_emb = (const float*)d_in[1];
    const float* Wih_f = (const float*)d_in[2];
    const float* Whh_f = (const float*)d_in[3];
    const float* bih_f = (const float*)d_in[4];
    const float* bhh_f = (const float*)d_in[5];
    const float* Wih_b = (const float*)d_in[6];
    const float* Whh_b = (const float*)d_in[7];
    const float* bih_b = (const float*)d_in[8];
    const float* bhh_b = (const float*)d_in[9];
    const float* Wih_c = (const float*)d_in[10];
    const float* Whh_c = (const float*)d_in[11];
    const float* bih_c = (const float*)d_in[12];
    const float* bhh_c = (const float*)d_in[13];
    const float* Wout  = (const float*)d_in[14];
    const float* bout  = (const float*)d_in[15];
    const float* h0f   = (const float*)d_in[16];
    const float* c0f   = (const float*)d_in[17];
    const float* h0b   = (const float*)d_in[18];
    const float* c0b   = (const float*)d_in[19];
    const float* h0c   = (const float*)d_in[20];
    const float* c0c   = (const float*)d_in[21];
    float* out = (float*)d_out;

    __half *seq, *comb, *hf, *hb, *hc;
    __half *wihf, *whhf, *wihb, *whhb, *wihc, *whhc;
    __half *gxf, *gxb, *gxc;
    float *cf, *cb, *cc;
    unsigned* bar;
    cudaGetSymbolAddress((void**)&seq,  g_seq);
    cudaGetSymbolAddress((void**)&gxf,  g_gxf);
    cudaGetSymbolAddress((void**)&gxb,  g_gxb);
    cudaGetSymbolAddress((void**)&gxc,  g_gxc);
    cudaGetSymbolAddress((void**)&comb, g_comb);
    cudaGetSymbolAddress((void**)&hf,   g_hf);
    cudaGetSymbolAddress((void**)&cf,   g_cf);
    cudaGetSymbolAddress((void**)&hb,   g_hb);
    cudaGetSymbolAddress((void**)&cb,   g_cb);
    cudaGetSymbolAddress((void**)&hc,   g_hc);
    cudaGetSymbolAddress((void**)&cc,   g_cc);
    cudaGetSymbolAddress((void**)&wihf, g_wihf);
    cudaGetSymbolAddress((void**)&whhf, g_whhf);
    cudaGetSymbolAddress((void**)&wihb, g_wihb);
    cudaGetSymbolAddress((void**)&whhb, g_whhb);
    cudaGetSymbolAddress((void**)&wihc, g_wihc);
    cudaGetSymbolAddress((void**)&whhc, g_whhc);
    cudaGetSymbolAddress((void**)&bar,  g_bar);

    __half* hfb[2] = {hf, hf + BSZ * HID};
    __half* hbb[2] = {hb, hb + BSZ * HID};
    __half* hcb[2] = {hc, hc + BSZ * H2};

    auto cvt = [](const float* in, __half* out_, int n) {
        int n4 = n / 4;
        cvt_kernel<<<(n4 + 255) / 256, 256>>>(
            (const float4*)in, (Half4*)out_, n4);
    };

    cvt(Wih_f, wihf, H4 * HID);
    cvt(Whh_f, whhf, H4 * HID);
    cvt(Wih_b, wihb, H4 * HID);
    cvt(Whh_b, whhb, H4 * HID);
    cvt(Wih_c, wihc, H8 * H2);
    cvt(Whh_c, whhc, H8 * H2);
    cvt(h0f, hfb[0], BSZ * HID);
    cvt(h0b, hbb[0], BSZ * HID);
    cvt(h0c, hcb[0], BSZ * H2);

    cudaMemcpyAsync(cf, c0f, BSZ * HID * sizeof(float), cudaMemcpyDeviceToDevice, 0);
    cudaMemcpyAsync(cb, c0b, BSZ * HID * sizeof(float), cudaMemcpyDeviceToDevice, 0);
    cudaMemcpyAsync(cc, c0c, BSZ * H2  * sizeof(float), cudaMemcpyDeviceToDevice, 0);

    {
        int total4 = BSZ * SEQ * (HID / 4);
        embed_kernel<<<(total4 + 255) / 256, 256>>>(x, W_emb, (Half4*)seq);
    }

    GemmSet Z = {};

    // Batched input projections for f and b cells (fp16 out)
    {
        GemmSet sf = Z;
        sf.A = seq; sf.W = wihf; sf.b0 = bih_f; sf.b1 = bhh_f; sf.C = gxf;
        sf.jx = H4 / 128;
        GemmSet sb = sf;
        sb.W = wihb; sb.b0 = bih_b; sb.b1 = bhh_b; sb.C = gxb;
        dim3 grid(H4 / 128, (SEQ * BSZ) / BM, 2);
        gemm_f16<<<grid, 256>>>(sf, sb, H4, HID);
    }

    // Persistent f/b recurrence chain (ONE launch, 64 steps)
    {
        cudaMemsetAsync(bar, 0, sizeof(unsigned), 0);
        ChainSet f = {};
        f.W = whhf; f.gx = gxf; f.hb0 = hfb[0]; f.hb1 = hfb[1];
        f.cbuf = cf; f.comb = comb; f.combStride = H2;
        f.Hd = HID; f.reverse = 0;
        ChainSet b = f;
        b.W = whhb; b.gx = gxb; b.hb0 = hbb[0]; b.hb1 = hbb[1];
        b.cbuf = cb; b.comb = comb + HID; b.reverse = 1;
        dim3 grid(HID / 32, BSZ / BM, 2);   // 128 blocks, all resident
        lstm_chain<<<grid, 256>>>(f, b, SEQ, bar, 128u);
    }

    // Batched input projection for combiner cell (fp16 out)
    {
        GemmSet sc = Z;
        sc.A = comb; sc.W = wihc; sc.b0 = bih_c; sc.b1 = bhh_c; sc.C = gxc;
        sc.jx = H8 / 128;
        dim3 grid(H8 / 128, (SEQ * BSZ) / BM, 1);
        gemm_f16<<<grid, 256>>>(sc, Z, H8, H2);
    }

    // Persistent combiner recurrence chain (ONE launch, 64 steps)
    {
        cudaMemsetAsync(bar, 0, sizeof(unsigned), 0);
        ChainSet c = {};
        c.W = whhc; c.gx = gxc; c.hb0 = hcb[0]; c.hb1 = hcb[1];
        c.cbuf = cc; c.comb = nullptr; c.combStride = 0;
        c.Hd = H2; c.reverse = 0;
        dim3 grid(H2 / 32, BSZ / BM, 1);    // 128 blocks, all resident
        lstm_chain<<<grid, 256>>>(c, c, SEQ, bar, 128u);
    }

    // output head: out = hc_final @ Wout^T + bout, fp32 weights read directly
    {
        dim3 grid(VOC / 128, BSZ / BM, 1);
        gemm_head<<<grid, 256>>>(hcb[0], Wout, bout, out, VOC, H2);
    }
}